// round 11
// baseline (speedup 1.0000x reference)
#include <cuda_runtime.h>
#include <cuda_fp16.h>
#include <cstdint>

#define N_NODES 100000
#define N_EDGES 1600000
#define N_GRAPH 100
#define IN_DIM 64
#define LATENT 128
#define LN_EPS 1e-5f

// ---------------- scratch (device globals; no allocation allowed) ----------------
__device__ uint32_t g_h16[(size_t)N_NODES * 64];     // node state, packed half2
__device__ uint32_t g_x16[(size_t)N_NODES * 64];     // xs, packed half2
__device__ int   g_cs[N_NODES];
__device__ int   g_cr[N_NODES];
__device__ float g_invs[N_NODES];
__device__ float g_invr[N_NODES];
__device__ int   g_start[N_NODES];
__device__ int   g_fill[N_NODES];
__device__ int   g_csr[N_EDGES];
__device__ int   g_cursor;
#define WCONV_WORDS (4096 + 4 * 8192)
__device__ uint32_t g_whi[WCONV_WORDS];
__device__ uint32_t g_wlo[WCONV_WORDS];

// ---------------- degree / CSR kernels ----------------
__global__ void k_zero_deg() {
    int i = blockIdx.x * blockDim.x + threadIdx.x;
    if (i < N_NODES) { g_cs[i] = 0; g_cr[i] = 0; }
    if (i == 0) g_cursor = 0;
}
__global__ void k_count(const int* __restrict__ senders, const int* __restrict__ receivers) {
    int e = blockIdx.x * blockDim.x + threadIdx.x;
    if (e < N_EDGES) {
        atomicAdd(&g_cs[senders[e]], 1);
        atomicAdd(&g_cr[receivers[e]], 1);
    }
}
__global__ void k_inv() {
    int i = blockIdx.x * blockDim.x + threadIdx.x;
    if (i < N_NODES) {
        g_invs[i] = rsqrtf((float)(g_cs[i] + 1));
        g_invr[i] = rsqrtf((float)(g_cr[i] + 1));
        int st = atomicAdd(&g_cursor, g_cr[i]);
        g_start[i] = st;
        g_fill[i] = st;
    }
}
__global__ void k_fill(const int* __restrict__ senders, const int* __restrict__ receivers) {
    int e = blockIdx.x * blockDim.x + threadIdx.x;
    if (e < N_EDGES) {
        int r = receivers[e];
        int pos = atomicAdd(&g_fill[r], 1);
        g_csr[pos] = senders[e];
    }
}

// ---------------- fp16 / mma helpers ----------------
__device__ __forceinline__ void hilo(float x, __half& h, float& res) {
    h = __float2half_rn(x);
    res = x - __half2float(h);
}
__device__ __forceinline__ uint32_t pack2(__half a, __half b) {
    __half2 h = __halves2half2(a, b);
    return *(uint32_t*)&h;
}
__device__ __forceinline__ void mma_f16(float c[4], const uint32_t a[4],
                                        uint32_t b0, uint32_t b1) {
    asm volatile(
        "mma.sync.aligned.m16n8k16.row.col.f32.f16.f16.f32 "
        "{%0,%1,%2,%3}, {%4,%5,%6,%7}, {%8,%9}, {%0,%1,%2,%3};"
        : "+f"(c[0]), "+f"(c[1]), "+f"(c[2]), "+f"(c[3])
        : "r"(a[0]), "r"(a[1]), "r"(a[2]), "r"(a[3]),
          "r"(b0), "r"(b1));
}
__device__ __forceinline__ uint32_t cvta_s(const void* p) {
    return (uint32_t)__cvta_generic_to_shared(p);
}
__device__ __forceinline__ void ldsm_x4(uint32_t r[4], uint32_t addr) {
    asm volatile("ldmatrix.sync.aligned.m8n8.x4.shared.b16 {%0,%1,%2,%3}, [%4];"
                 : "=r"(r[0]), "=r"(r[1]), "=r"(r[2]), "=r"(r[3]) : "r"(addr));
}
__device__ __forceinline__ void ldsm_x2(uint32_t& r0, uint32_t& r1, uint32_t addr) {
    asm volatile("ldmatrix.sync.aligned.m8n8.x2.shared.b16 {%0,%1}, [%2];"
                 : "=r"(r0), "=r"(r1) : "r"(addr));
}

// ---------------- weight pre-conversion ----------------
__global__ void k_wconv(const float* __restrict__ embed_w, const float* __restrict__ mlp_w) {
    int i = blockIdx.x * blockDim.x + threadIdx.x;
    if (i >= WCONV_WORDS) return;
    float v0, v1;
    if (i < 4096) {
        int n = i >> 5, kp = i & 31;
        v0 = embed_w[(size_t)(2 * kp) * 128 + n];
        v1 = embed_w[(size_t)(2 * kp + 1) * 128 + n];
    } else {
        int j = i - 4096;
        int g = j >> 13;
        int r = j & 8191;
        int n = r >> 6, kp = r & 63;
        const float* W = mlp_w + (size_t)g * 128 * 128;
        v0 = W[(size_t)(2 * kp) * 128 + n];
        v1 = W[(size_t)(2 * kp + 1) * 128 + n];
    }
    __half h0, h1; float r0, r1;
    hilo(v0, h0, r0); hilo(v1, h1, r1);
    g_whi[i] = pack2(h0, h1);
    g_wlo[i] = pack2(__float2half_rn(r0), __float2half_rn(r1));
}

#define S2  36    // B / embed-A stride (words): 36 mod 32 = 4 -> ldmatrix conflict-free
#define S2F 68    // full-K A stride (words): 68 mod 32 = 4 -> conflict-free
#define TILEW (128 * S2)

// ---------------- embed GEMM: fp32 A, hi/lo split (3 passes), K=64 ----------------
__global__ __launch_bounds__(512, 2)
void k_embed(const float* __restrict__ A,
             const uint32_t* __restrict__ Whi, const uint32_t* __restrict__ Wlo,
             const float* __restrict__ bias, uint32_t* __restrict__ C16, int M) {
    extern __shared__ uint32_t sm[];
    uint32_t* sAhi = sm;
    uint32_t* sBhi = sm + TILEW;
    uint32_t* sBlo = sm + 2 * TILEW;
    uint32_t* sAlo = sm + 3 * TILEW;
    float*    sBias = (float*)(sm + 4 * TILEW);

    const int tid  = threadIdx.x;
    const int lane = tid & 31;
    const int wid  = tid >> 5;
    const int grp  = lane >> 2;
    const int tig  = lane & 3;
    const int wm   = wid & 3;
    const int wn   = wid >> 2;
    const int row0 = blockIdx.x * 128;

    const int lane7 = lane & 7;
    const int lhalf = (lane >> 3) & 1;
    const int lquad = lane >> 4;

    if (tid < 128) sBias[tid] = bias[tid];

    float acc[2][4][4];
#pragma unroll
    for (int i = 0; i < 2; i++)
#pragma unroll
        for (int j = 0; j < 4; j++)
#pragma unroll
            for (int q = 0; q < 4; q++) acc[i][j][q] = 0.f;

    // stage A [128 x 64] fp32 -> fp16 hi/lo
#pragma unroll
    for (int it = 0; it < 4; it++) {
        int i  = tid + it * 512;
        int r  = i >> 4;
        int c4 = (i & 15) * 4;
        float4 v = make_float4(0.f, 0.f, 0.f, 0.f);
        if (row0 + r < M)
            v = *(const float4*)&A[(size_t)(row0 + r) * 64 + c4];
        __half h0, h1, h2, h3; float r0, r1, r2, r3;
        hilo(v.x, h0, r0); hilo(v.y, h1, r1);
        hilo(v.z, h2, r2); hilo(v.w, h3, r3);
        int w = r * S2 + (c4 >> 1);
        *(uint2*)&sAhi[w] = make_uint2(pack2(h0, h1), pack2(h2, h3));
        *(uint2*)&sAlo[w] = make_uint2(
            pack2(__float2half_rn(r0), __float2half_rn(r1)),
            pack2(__float2half_rn(r2), __float2half_rn(r3)));
    }
    // stage B [128 n x 32 kp]
#pragma unroll
    for (int it = 0; it < 2; it++) {
        int i = tid + it * 512;
        int n = i >> 3;
        int q = (i & 7) * 4;
        if (q < 32) {
            *(uint4*)&sBhi[n * S2 + q] = *(const uint4*)&Whi[n * 32 + q];
            *(uint4*)&sBlo[n * S2 + q] = *(const uint4*)&Wlo[n * 32 + q];
        }
    }
    __syncthreads();

    // ldmatrix base addresses
    const uint32_t aHiB = cvta_s(&sAhi[(wm * 32 + lane7 + lhalf * 8) * S2 + lquad * 4]);
    const uint32_t aLoB = cvta_s(&sAlo[(wm * 32 + lane7 + lhalf * 8) * S2 + lquad * 4]);
    const uint32_t bHiB = cvta_s(&sBhi[(wn * 32 + lane7) * S2 + lhalf * 4]);
    const uint32_t bLoB = cvta_s(&sBlo[(wn * 32 + lane7) * S2 + lhalf * 4]);

#pragma unroll
    for (int ks = 0; ks < 4; ks++) {
        const int kb = ks * 8;
        uint32_t aH[2][4], aL[2][4];
#pragma unroll
        for (int mt = 0; mt < 2; mt++) {
            ldsm_x4(aH[mt], aHiB + ((mt * 16 * S2 + kb) << 2));
            ldsm_x4(aL[mt], aLoB + ((mt * 16 * S2 + kb) << 2));
        }
#pragma unroll
        for (int nt = 0; nt < 4; nt++) {
            uint32_t bh0, bh1, bl0, bl1;
            ldsm_x2(bh0, bh1, bHiB + ((nt * 8 * S2 + kb) << 2));
            ldsm_x2(bl0, bl1, bLoB + ((nt * 8 * S2 + kb) << 2));
#pragma unroll
            for (int mt = 0; mt < 2; mt++) {
                mma_f16(acc[mt][nt], aH[mt], bh0, bh1);
                mma_f16(acc[mt][nt], aH[mt], bl0, bl1);
                mma_f16(acc[mt][nt], aL[mt], bh0, bh1);
            }
        }
    }

#pragma unroll
    for (int mt = 0; mt < 2; mt++) {
        int ra = row0 + wm * 32 + mt * 16 + grp;
        int rb = ra + 8;
#pragma unroll
        for (int nt = 0; nt < 4; nt++) {
            int col = wn * 32 + nt * 8 + 2 * tig;
            float b0 = sBias[col], b1 = sBias[col + 1];
            __half2 pa2 = __floats2half2_rn(acc[mt][nt][0] + b0, acc[mt][nt][1] + b1);
            __half2 pb2 = __floats2half2_rn(acc[mt][nt][2] + b0, acc[mt][nt][3] + b1);
            if (ra < M) C16[(size_t)ra * 64 + (col >> 1)] = *(uint32_t*)&pa2;
            if (rb < M) C16[(size_t)rb * 64 + (col >> 1)] = *(uint32_t*)&pb2;
        }
    }
}
#define SM_EMBED (4 * TILEW * 4 + 128 * 4)

// ---------------- fused 2-layer MLP: xs = relu(relu(h@W1+b1)@W2+b2) * invs ----------------
__global__ __launch_bounds__(512, 2)
void k_mlp(const uint32_t* __restrict__ A16,
           const uint32_t* __restrict__ W1hi, const uint32_t* __restrict__ W1lo,
           const uint32_t* __restrict__ W2hi, const uint32_t* __restrict__ W2lo,
           const float* __restrict__ b1, const float* __restrict__ b2,
           uint32_t* __restrict__ C16, int M) {
    extern __shared__ uint32_t sm[];
    uint32_t* sA   = sm;                       // 128 x S2F (full K, fp16 words)
    uint32_t* sBhi = sm + 128 * S2F;
    uint32_t* sBlo = sBhi + TILEW;
    float*    sB1  = (float*)(sBlo + TILEW);
    float*    sB2  = sB1 + 128;

    const int tid  = threadIdx.x;
    const int lane = tid & 31;
    const int wid  = tid >> 5;
    const int grp  = lane >> 2;
    const int tig  = lane & 3;
    const int wm   = wid & 3;
    const int wn   = wid >> 2;
    const int row0 = blockIdx.x * 128;

    const int lane7 = lane & 7;
    const int lhalf = (lane >> 3) & 1;
    const int lquad = lane >> 4;

    if (tid < 128) { sB1[tid] = b1[tid]; sB2[tid] = b2[tid]; }

    // stage A full-K [128 rows x 64 words]
#pragma unroll
    for (int it = 0; it < 4; it++) {
        int i = tid + it * 512;
        int r = i >> 4;
        int q = (i & 15) * 4;
        uint4 v = make_uint4(0, 0, 0, 0);
        if (row0 + r < M)
            v = *(const uint4*)&A16[(size_t)(row0 + r) * 64 + q];
        *(uint4*)&sA[r * S2F + q] = v;
    }

    float acc[2][4][4];
#pragma unroll
    for (int i = 0; i < 2; i++)
#pragma unroll
        for (int j = 0; j < 4; j++)
#pragma unroll
            for (int q = 0; q < 4; q++) acc[i][j][q] = 0.f;

    const uint32_t aB   = cvta_s(&sA[(wm * 32 + lane7 + lhalf * 8) * S2F + lquad * 4]);
    const uint32_t bHiB = cvta_s(&sBhi[(wn * 32 + lane7) * S2 + lhalf * 4]);
    const uint32_t bLoB = cvta_s(&sBlo[(wn * 32 + lane7) * S2 + lhalf * 4]);

    // ================= GEMM 1 =================
    for (int ch = 0; ch < 2; ch++) {
        if (ch) __syncthreads();
#pragma unroll
        for (int it = 0; it < 2; it++) {
            int i = tid + it * 512;
            int n = i >> 3;
            int q = (i & 7) * 4;
            int gw = n * 64 + ch * 32 + q;
            *(uint4*)&sBhi[n * S2 + q] = *(const uint4*)&W1hi[gw];
            *(uint4*)&sBlo[n * S2 + q] = *(const uint4*)&W1lo[gw];
        }
        __syncthreads();
#pragma unroll
        for (int ks = 0; ks < 4; ks++) {
            const int kb = ks * 8;
            uint32_t aH[2][4];
#pragma unroll
            for (int mt = 0; mt < 2; mt++)
                ldsm_x4(aH[mt], aB + ((mt * 16 * S2F + ch * 32 + kb) << 2));
#pragma unroll
            for (int nt = 0; nt < 4; nt++) {
                uint32_t bh0, bh1, bl0, bl1;
                ldsm_x2(bh0, bh1, bHiB + ((nt * 8 * S2 + kb) << 2));
                ldsm_x2(bl0, bl1, bLoB + ((nt * 8 * S2 + kb) << 2));
#pragma unroll
                for (int mt = 0; mt < 2; mt++) {
                    mma_f16(acc[mt][nt], aH[mt], bh0, bh1);
                    mma_f16(acc[mt][nt], aH[mt], bl0, bl1);
                }
            }
        }
    }
    __syncthreads();

    // hidden = relu(acc + b1) -> overwrite sA
#pragma unroll
    for (int mt = 0; mt < 2; mt++) {
        int lr = wm * 32 + mt * 16 + grp;
#pragma unroll
        for (int nt = 0; nt < 4; nt++) {
            int col = wn * 32 + nt * 8 + 2 * tig;
            float b0 = sB1[col], bq = sB1[col + 1];
            float v0 = fmaxf(acc[mt][nt][0] + b0, 0.f);
            float v1 = fmaxf(acc[mt][nt][1] + bq, 0.f);
            float v2 = fmaxf(acc[mt][nt][2] + b0, 0.f);
            float v3 = fmaxf(acc[mt][nt][3] + bq, 0.f);
            sA[lr * S2F + (col >> 1)]       = pack2(__float2half_rn(v0), __float2half_rn(v1));
            sA[(lr + 8) * S2F + (col >> 1)] = pack2(__float2half_rn(v2), __float2half_rn(v3));
            acc[mt][nt][0] = 0.f; acc[mt][nt][1] = 0.f;
            acc[mt][nt][2] = 0.f; acc[mt][nt][3] = 0.f;
        }
    }

    // ================= GEMM 2 =================
    for (int ch = 0; ch < 2; ch++) {
        if (ch) __syncthreads();
#pragma unroll
        for (int it = 0; it < 2; it++) {
            int i = tid + it * 512;
            int n = i >> 3;
            int q = (i & 7) * 4;
            int gw = n * 64 + ch * 32 + q;
            *(uint4*)&sBhi[n * S2 + q] = *(const uint4*)&W2hi[gw];
            *(uint4*)&sBlo[n * S2 + q] = *(const uint4*)&W2lo[gw];
        }
        __syncthreads();
#pragma unroll
        for (int ks = 0; ks < 4; ks++) {
            const int kb = ks * 8;
            uint32_t aH[2][4];
#pragma unroll
            for (int mt = 0; mt < 2; mt++)
                ldsm_x4(aH[mt], aB + ((mt * 16 * S2F + ch * 32 + kb) << 2));
#pragma unroll
            for (int nt = 0; nt < 4; nt++) {
                uint32_t bh0, bh1, bl0, bl1;
                ldsm_x2(bh0, bh1, bHiB + ((nt * 8 * S2 + kb) << 2));
                ldsm_x2(bl0, bl1, bLoB + ((nt * 8 * S2 + kb) << 2));
#pragma unroll
                for (int mt = 0; mt < 2; mt++) {
                    mma_f16(acc[mt][nt], aH[mt], bh0, bh1);
                    mma_f16(acc[mt][nt], aH[mt], bl0, bl1);
                }
            }
        }
    }

    // epilogue: relu(acc + b2) * invs -> xs16
#pragma unroll
    for (int mt = 0; mt < 2; mt++) {
        int ra = row0 + wm * 32 + mt * 16 + grp;
        int rb = ra + 8;
        float sa = (ra < M) ? g_invs[ra] : 0.f;
        float sb = (rb < M) ? g_invs[rb] : 0.f;
#pragma unroll
        for (int nt = 0; nt < 4; nt++) {
            int col = wn * 32 + nt * 8 + 2 * tig;
            float b0 = sB2[col], bq = sB2[col + 1];
            float v0 = fmaxf(acc[mt][nt][0] + b0, 0.f) * sa;
            float v1 = fmaxf(acc[mt][nt][1] + bq, 0.f) * sa;
            float v2 = fmaxf(acc[mt][nt][2] + b0, 0.f) * sb;
            float v3 = fmaxf(acc[mt][nt][3] + bq, 0.f) * sb;
            __half2 pa2 = __floats2half2_rn(v0, v1);
            __half2 pb2 = __floats2half2_rn(v2, v3);
            if (ra < M) C16[(size_t)ra * 64 + (col >> 1)] = *(uint32_t*)&pa2;
            if (rb < M) C16[(size_t)rb * 64 + (col >> 1)] = *(uint32_t*)&pb2;
        }
    }
}
#define SM_MLP ((128 * S2F + 2 * TILEW) * 4 + 256 * 4)

// ---------------- fused CSR gather (fp16) + skip + LayerNorm (fp16 h) ----------------
__global__ __launch_bounds__(256)
void k_gln(const uint32_t* __restrict__ xs16, uint32_t* __restrict__ h16,
           const float* __restrict__ scale, const float* __restrict__ offset) {
    int node = (blockIdx.x * blockDim.x + threadIdx.x) >> 5;
    int lane = threadIdx.x & 31;
    if (node >= N_NODES) return;
    const int c = lane * 4;
    const int w = lane * 2;

    float4 acc;
    {
        uint2 sv = *(const uint2*)&xs16[(size_t)node * 64 + w];
        float2 f0 = __half22float2(*(__half2*)&sv.x);
        float2 f1 = __half22float2(*(__half2*)&sv.y);
        acc = make_float4(f0.x, f0.y, f1.x, f1.y);
    }
    const int beg = g_start[node];
    const int end = beg + g_cr[node];

    for (int base = beg; base < end; base += 32) {
        int idx = (base + lane < end) ? g_csr[base + lane] : 0;
        int m = min(32, end - base);
        int j = 0;
        for (; j + 4 <= m; j += 4) {
            int s0 = __shfl_sync(0xffffffffu, idx, j);
            int s1 = __shfl_sync(0xffffffffu, idx, j + 1);
            int s2 = __shfl_sync(0xffffffffu, idx, j + 2);
            int s3 = __shfl_sync(0xffffffffu, idx, j + 3);
            uint2 v0 = *(const uint2*)&xs16[(size_t)s0 * 64 + w];
            uint2 v1 = *(const uint2*)&xs16[(size_t)s1 * 64 + w];
            uint2 v2 = *(const uint2*)&xs16[(size_t)s2 * 64 + w];
            uint2 v3 = *(const uint2*)&xs16[(size_t)s3 * 64 + w];
            float2 e;
            e = __half22float2(*(__half2*)&v0.x); acc.x += e.x; acc.y += e.y;
            e = __half22float2(*(__half2*)&v1.x); acc.x += e.x; acc.y += e.y;
            e = __half22float2(*(__half2*)&v2.x); acc.x += e.x; acc.y += e.y;
            e = __half22float2(*(__half2*)&v3.x); acc.x += e.x; acc.y += e.y;
            e = __half22float2(*(__half2*)&v0.y); acc.z += e.x; acc.w += e.y;
            e = __half22float2(*(__half2*)&v1.y); acc.z += e.x; acc.w += e.y;
            e = __half22float2(*(__half2*)&v2.y); acc.z += e.x; acc.w += e.y;
            e = __half22float2(*(__half2*)&v3.y); acc.z += e.x; acc.w += e.y;
        }
        for (; j < m; j++) {
            int s = __shfl_sync(0xffffffffu, idx, j);
            uint2 v = *(const uint2*)&xs16[(size_t)s * 64 + w];
            float2 f0 = __half22float2(*(__half2*)&v.x);
            float2 f1 = __half22float2(*(__half2*)&v.y);
            acc.x += f0.x; acc.y += f0.y; acc.z += f1.x; acc.w += f1.y;
        }
    }

    float ir = g_invr[node];
    float4 vh;
    {
        uint2 hv = *(const uint2*)&h16[(size_t)node * 64 + w];
        float2 f0 = __half22float2(*(__half2*)&hv.x);
        float2 f1 = __half22float2(*(__half2*)&hv.y);
        vh = make_float4(f0.x, f0.y, f1.x, f1.y);
    }
    float4 y;
    y.x = acc.x * ir + vh.x; y.y = acc.y * ir + vh.y;
    y.z = acc.z * ir + vh.z; y.w = acc.w * ir + vh.w;

    float sum = y.x + y.y + y.z + y.w;
    float sq  = y.x * y.x + y.y * y.y + y.z * y.z + y.w * y.w;
#pragma unroll
    for (int o = 16; o; o >>= 1) {
        sum += __shfl_xor_sync(0xffffffffu, sum, o);
        sq  += __shfl_xor_sync(0xffffffffu, sq, o);
    }
    float mean = sum * (1.f / 128.f);
    float var  = sq * (1.f / 128.f) - mean * mean;
    float rs = rsqrtf(var + LN_EPS);
    float4 scv = *(const float4*)&scale[c];
    float4 ofv = *(const float4*)&offset[c];
    y.x = (y.x - mean) * rs * scv.x + ofv.x;
    y.y = (y.y - mean) * rs * scv.y + ofv.y;
    y.z = (y.z - mean) * rs * scv.z + ofv.z;
    y.w = (y.w - mean) * rs * scv.w + ofv.w;
    __half2 p0 = __floats2half2_rn(y.x, y.y);
    __half2 p1 = __floats2half2_rn(y.z, y.w);
    *(uint2*)&h16[(size_t)node * 64 + w] = make_uint2(*(uint32_t*)&p0, *(uint32_t*)&p1);
}

// ---------------- pool (fp16 h) + decode ----------------
__global__ __launch_bounds__(64)
void k_pool(const uint32_t* __restrict__ h16, const float* __restrict__ dec_w,
            const float* __restrict__ dec_b, float* __restrict__ out) {
    int g = blockIdx.x;
    int w = threadIdx.x;
    const int per = N_NODES / N_GRAPH;
    const uint32_t* base = h16 + (size_t)g * per * 64;
    float s0 = 0.f, s1 = 0.f;
#pragma unroll 8
    for (int r = 0; r < per; r++) {
        uint32_t v = base[(size_t)r * 64 + w];
        float2 f = __half22float2(*(__half2*)&v);
        s0 += f.x; s1 += f.y;
    }
    float val = (s0 * dec_w[2 * w] + s1 * dec_w[2 * w + 1]) * (1.f / (float)per);
    __shared__ float red[2];
#pragma unroll
    for (int o = 16; o; o >>= 1) val += __shfl_xor_sync(0xffffffffu, val, o);
    if ((threadIdx.x & 31) == 0) red[threadIdx.x >> 5] = val;
    __syncthreads();
    if (threadIdx.x == 0) out[g] = red[0] + red[1] + dec_b[0];
}

// ---------------- launch ----------------
extern "C" void kernel_launch(void* const* d_in, const int* in_sizes, int n_in,
                              void* d_out, int out_size) {
    const float* nodes     = (const float*)d_in[0];
    const int*   senders   = (const int*)d_in[1];
    const int*   receivers = (const int*)d_in[2];
    const float* embed_w   = (const float*)d_in[4];
    const float* embed_b   = (const float*)d_in[5];
    const float* mlp_w     = (const float*)d_in[6];
    const float* mlp_b     = (const float*)d_in[7];
    const float* ln_scale  = (const float*)d_in[8];
    const float* ln_offset = (const float*)d_in[9];
    const float* dec_w     = (const float*)d_in[10];
    const float* dec_b     = (const float*)d_in[11];
    float* out = (float*)d_out;

    uint32_t *ph16, *px16, *pwhi, *pwlo;
    cudaGetSymbolAddress((void**)&ph16, g_h16);
    cudaGetSymbolAddress((void**)&px16, g_x16);
    cudaGetSymbolAddress((void**)&pwhi, g_whi);
    cudaGetSymbolAddress((void**)&pwlo, g_wlo);

    cudaFuncSetAttribute(k_embed, cudaFuncAttributeMaxDynamicSharedMemorySize, SM_EMBED);
    cudaFuncSetAttribute(k_mlp,   cudaFuncAttributeMaxDynamicSharedMemorySize, SM_MLP);

    static cudaStream_t s2 = nullptr;
    static cudaEvent_t evFork = nullptr, evInv = nullptr, evJoin = nullptr;
    if (!s2) {
        cudaStreamCreateWithFlags(&s2, cudaStreamNonBlocking);
        cudaEventCreateWithFlags(&evFork, cudaEventDisableTiming);
        cudaEventCreateWithFlags(&evInv, cudaEventDisableTiming);
        cudaEventCreateWithFlags(&evJoin, cudaEventDisableTiming);
    }

    // ---- fork: CSR build on s2 ----
    cudaEventRecord(evFork, 0);
    cudaStreamWaitEvent(s2, evFork, 0);
    k_zero_deg<<<(N_NODES + 255) / 256, 256, 0, s2>>>();
    k_count<<<(N_EDGES + 255) / 256, 256, 0, s2>>>(senders, receivers);
    k_inv<<<(N_NODES + 255) / 256, 256, 0, s2>>>();
    cudaEventRecord(evInv, s2);
    k_fill<<<(N_EDGES + 255) / 256, 256, 0, s2>>>(senders, receivers);
    cudaEventRecord(evJoin, s2);

    const int gemm_grid = (N_NODES + 127) / 128;

    k_wconv<<<(WCONV_WORDS + 255) / 256, 256>>>(embed_w, mlp_w);
    k_embed<<<gemm_grid, 512, SM_EMBED>>>(nodes, pwhi, pwlo, embed_b, ph16, N_NODES);

    const uint32_t* whi_mlp[4];
    const uint32_t* wlo_mlp[4];
    for (int g = 0; g < 4; g++) {
        whi_mlp[g] = pwhi + 4096 + g * 8192;
        wlo_mlp[g] = pwlo + 4096 + g * 8192;
    }

    const int row_grid = (N_NODES * 32 + 255) / 256;

    cudaStreamWaitEvent(0, evInv, 0);

    for (int s = 0; s < 2; s++) {
        const float* b0 = mlp_b + (size_t)(s * 2 + 0) * LATENT;
        const float* b1 = mlp_b + (size_t)(s * 2 + 1) * LATENT;

        k_mlp<<<gemm_grid, 512, SM_MLP>>>(ph16,
                                          whi_mlp[s * 2], wlo_mlp[s * 2],
                                          whi_mlp[s * 2 + 1], wlo_mlp[s * 2 + 1],
                                          b0, b1, px16, N_NODES);
        if (s == 0) cudaStreamWaitEvent(0, evJoin, 0);
        k_gln<<<row_grid, 256>>>(px16, ph16, ln_scale + s * LATENT, ln_offset + s * LATENT);
    }

    k_pool<<<N_GRAPH, 64>>>(ph16, dec_w, dec_b, out);
}

// round 12
// speedup vs baseline: 1.0340x; 1.0340x over previous
#include <cuda_runtime.h>
#include <cuda_fp16.h>
#include <cstdint>

#define N_NODES 100000
#define N_EDGES 1600000
#define N_GRAPH 100
#define IN_DIM 64
#define LATENT 128
#define LN_EPS 1e-5f

// ---------------- scratch (device globals; no allocation allowed) ----------------
__device__ uint32_t g_h16[(size_t)N_NODES * 64];     // node state, packed half2
__device__ uint32_t g_x16[(size_t)N_NODES * 64];     // xs, packed half2
__device__ int   g_cs[N_NODES];
__device__ int   g_cr[N_NODES];
__device__ float g_invs[N_NODES];
__device__ float g_invr[N_NODES];
__device__ int   g_start[N_NODES];
__device__ int   g_fill[N_NODES];
__device__ int   g_csr[N_EDGES];
__device__ int   g_cursor;
#define WCONV_WORDS (4096 + 4 * 8192)
__device__ uint32_t g_whi[WCONV_WORDS];
__device__ uint32_t g_wlo[WCONV_WORDS];

// ---------------- degree / CSR kernels ----------------
__global__ void k_zero_deg() {
    int i = blockIdx.x * blockDim.x + threadIdx.x;
    if (i < N_NODES) { g_cs[i] = 0; g_cr[i] = 0; }
    if (i == 0) g_cursor = 0;
}
__global__ void k_count(const int* __restrict__ senders, const int* __restrict__ receivers) {
    int e = blockIdx.x * blockDim.x + threadIdx.x;
    if (e < N_EDGES) {
        atomicAdd(&g_cs[senders[e]], 1);
        atomicAdd(&g_cr[receivers[e]], 1);
    }
}
__global__ void k_inv() {
    int i = blockIdx.x * blockDim.x + threadIdx.x;
    if (i < N_NODES) {
        g_invs[i] = rsqrtf((float)(g_cs[i] + 1));
        g_invr[i] = rsqrtf((float)(g_cr[i] + 1));
        int st = atomicAdd(&g_cursor, g_cr[i]);
        g_start[i] = st;
        g_fill[i] = st;
    }
}
__global__ void k_fill(const int* __restrict__ senders, const int* __restrict__ receivers) {
    int e = blockIdx.x * blockDim.x + threadIdx.x;
    if (e < N_EDGES) {
        int r = receivers[e];
        int pos = atomicAdd(&g_fill[r], 1);
        g_csr[pos] = senders[e];
    }
}

// ---------------- fp16 helpers ----------------
__device__ __forceinline__ void hilo(float x, __half& h, float& res) {
    h = __float2half_rn(x);
    res = x - __half2float(h);
}
__device__ __forceinline__ uint32_t pack2(__half a, __half b) {
    __half2 h = __halves2half2(a, b);
    return *(uint32_t*)&h;
}
__device__ __forceinline__ void mma_f16(float c[4], const uint32_t a[4],
                                        uint32_t b0, uint32_t b1) {
    asm volatile(
        "mma.sync.aligned.m16n8k16.row.col.f32.f16.f16.f32 "
        "{%0,%1,%2,%3}, {%4,%5,%6,%7}, {%8,%9}, {%0,%1,%2,%3};"
        : "+f"(c[0]), "+f"(c[1]), "+f"(c[2]), "+f"(c[3])
        : "r"(a[0]), "r"(a[1]), "r"(a[2]), "r"(a[3]),
          "r"(b0), "r"(b1));
}

// ---------------- weight pre-conversion ----------------
__global__ void k_wconv(const float* __restrict__ embed_w, const float* __restrict__ mlp_w) {
    int i = blockIdx.x * blockDim.x + threadIdx.x;
    if (i >= WCONV_WORDS) return;
    float v0, v1;
    if (i < 4096) {
        int n = i >> 5, kp = i & 31;
        v0 = embed_w[(size_t)(2 * kp) * 128 + n];
        v1 = embed_w[(size_t)(2 * kp + 1) * 128 + n];
    } else {
        int j = i - 4096;
        int g = j >> 13;
        int r = j & 8191;
        int n = r >> 6, kp = r & 63;
        const float* W = mlp_w + (size_t)g * 128 * 128;
        v0 = W[(size_t)(2 * kp) * 128 + n];
        v1 = W[(size_t)(2 * kp + 1) * 128 + n];
    }
    __half h0, h1; float r0, r1;
    hilo(v0, h0, r0); hilo(v1, h1, r1);
    g_whi[i] = pack2(h0, h1);
    g_wlo[i] = pack2(__float2half_rn(r0), __float2half_rn(r1));
}

#define S2  36    // B chunk stride (words)
#define S2F 68    // A full-K stride (words)
#define TILEW (128 * S2)

// ---------------- embed GEMM: fp32 A, hi/lo split (3 passes), K=64 ----------------
__global__ __launch_bounds__(512, 2)
void k_embed(const float* __restrict__ A,
             const uint32_t* __restrict__ Whi, const uint32_t* __restrict__ Wlo,
             const float* __restrict__ bias, uint32_t* __restrict__ C16, int M) {
    extern __shared__ uint32_t sm[];
    uint32_t* sAhi = sm;
    uint32_t* sBhi = sm + TILEW;
    uint32_t* sBlo = sm + 2 * TILEW;
    uint32_t* sAlo = sm + 3 * TILEW;
    float*    sBias = (float*)(sm + 4 * TILEW);

    const int tid  = threadIdx.x;
    const int lane = tid & 31;
    const int wid  = tid >> 5;
    const int grp  = lane >> 2;
    const int tig  = lane & 3;
    const int wm   = wid & 3;
    const int wn   = wid >> 2;
    const int row0 = blockIdx.x * 128;

    if (tid < 128) sBias[tid] = bias[tid];

    float acc[2][4][4];
#pragma unroll
    for (int i = 0; i < 2; i++)
#pragma unroll
        for (int j = 0; j < 4; j++)
#pragma unroll
            for (int q = 0; q < 4; q++) acc[i][j][q] = 0.f;

    // stage A [128 x 64] fp32 -> fp16 hi/lo
#pragma unroll
    for (int it = 0; it < 4; it++) {
        int i  = tid + it * 512;
        int r  = i >> 4;
        int c4 = (i & 15) * 4;
        float4 v = make_float4(0.f, 0.f, 0.f, 0.f);
        if (row0 + r < M)
            v = *(const float4*)&A[(size_t)(row0 + r) * 64 + c4];
        __half h0, h1, h2, h3; float r0, r1, r2, r3;
        hilo(v.x, h0, r0); hilo(v.y, h1, r1);
        hilo(v.z, h2, r2); hilo(v.w, h3, r3);
        int w = r * S2 + (c4 >> 1);
        *(uint2*)&sAhi[w] = make_uint2(pack2(h0, h1), pack2(h2, h3));
        *(uint2*)&sAlo[w] = make_uint2(
            pack2(__float2half_rn(r0), __float2half_rn(r1)),
            pack2(__float2half_rn(r2), __float2half_rn(r3)));
    }
    // stage B [128 n x 32 kp]
#pragma unroll
    for (int it = 0; it < 2; it++) {
        int i = tid + it * 512;
        int n = i >> 3;
        int q = (i & 7) * 4;
        if (q < 32) {
            *(uint4*)&sBhi[n * S2 + q] = *(const uint4*)&Whi[n * 32 + q];
            *(uint4*)&sBlo[n * S2 + q] = *(const uint4*)&Wlo[n * 32 + q];
        }
    }
    __syncthreads();

#pragma unroll
    for (int ks = 0; ks < 4; ks++) {
        const int kb = ks * 8;
        uint32_t aH[2][4], aL[2][4];
#pragma unroll
        for (int mt = 0; mt < 2; mt++) {
            int base = (wm * 32 + mt * 16 + grp) * S2 + kb + tig;
            aH[mt][0] = sAhi[base];
            aH[mt][1] = sAhi[base + 8 * S2];
            aH[mt][2] = sAhi[base + 4];
            aH[mt][3] = sAhi[base + 8 * S2 + 4];
            aL[mt][0] = sAlo[base];
            aL[mt][1] = sAlo[base + 8 * S2];
            aL[mt][2] = sAlo[base + 4];
            aL[mt][3] = sAlo[base + 8 * S2 + 4];
        }
#pragma unroll
        for (int nt = 0; nt < 4; nt++) {
            int bb = (wn * 32 + nt * 8 + grp) * S2 + kb + tig;
            uint32_t bh0 = sBhi[bb], bh1 = sBhi[bb + 4];
            uint32_t bl0 = sBlo[bb], bl1 = sBlo[bb + 4];
#pragma unroll
            for (int mt = 0; mt < 2; mt++) {
                mma_f16(acc[mt][nt], aH[mt], bh0, bh1);
                mma_f16(acc[mt][nt], aH[mt], bl0, bl1);
                mma_f16(acc[mt][nt], aL[mt], bh0, bh1);
            }
        }
    }

#pragma unroll
    for (int mt = 0; mt < 2; mt++) {
        int ra = row0 + wm * 32 + mt * 16 + grp;
        int rb = ra + 8;
#pragma unroll
        for (int nt = 0; nt < 4; nt++) {
            int col = wn * 32 + nt * 8 + 2 * tig;
            float b0 = sBias[col], b1 = sBias[col + 1];
            __half2 pa2 = __floats2half2_rn(acc[mt][nt][0] + b0, acc[mt][nt][1] + b1);
            __half2 pb2 = __floats2half2_rn(acc[mt][nt][2] + b0, acc[mt][nt][3] + b1);
            if (ra < M) C16[(size_t)ra * 64 + (col >> 1)] = *(uint32_t*)&pa2;
            if (rb < M) C16[(size_t)rb * 64 + (col >> 1)] = *(uint32_t*)&pb2;
        }
    }
}
#define SM_EMBED (4 * TILEW * 4 + 128 * 4)

// ---------------- fused 2-layer MLP: xs = relu(relu(h@W1+b1)@W2+b2) * invs ----------------
__global__ __launch_bounds__(512, 2)
void k_mlp(const uint32_t* __restrict__ A16,
           const uint32_t* __restrict__ W1hi, const uint32_t* __restrict__ W1lo,
           const uint32_t* __restrict__ W2hi, const uint32_t* __restrict__ W2lo,
           const float* __restrict__ b1, const float* __restrict__ b2,
           uint32_t* __restrict__ C16, int M) {
    extern __shared__ uint32_t sm[];
    uint32_t* sA   = sm;                       // 128 x S2F (full K, fp16 words)
    uint32_t* sBhi = sm + 128 * S2F;
    uint32_t* sBlo = sBhi + TILEW;
    float*    sB1  = (float*)(sBlo + TILEW);
    float*    sB2  = sB1 + 128;

    const int tid  = threadIdx.x;
    const int lane = tid & 31;
    const int wid  = tid >> 5;
    const int grp  = lane >> 2;
    const int tig  = lane & 3;
    const int wm   = wid & 3;
    const int wn   = wid >> 2;
    const int row0 = blockIdx.x * 128;

    if (tid < 128) { sB1[tid] = b1[tid]; sB2[tid] = b2[tid]; }

    // stage A full-K [128 rows x 64 words]
#pragma unroll
    for (int it = 0; it < 4; it++) {
        int i = tid + it * 512;
        int r = i >> 4;
        int q = (i & 15) * 4;
        uint4 v = make_uint4(0, 0, 0, 0);
        if (row0 + r < M)
            v = *(const uint4*)&A16[(size_t)(row0 + r) * 64 + q];
        *(uint4*)&sA[r * S2F + q] = v;
    }

    float acc[2][4][4];
#pragma unroll
    for (int i = 0; i < 2; i++)
#pragma unroll
        for (int j = 0; j < 4; j++)
#pragma unroll
            for (int q = 0; q < 4; q++) acc[i][j][q] = 0.f;

    // ================= GEMM 1 =================
    for (int ch = 0; ch < 2; ch++) {
        if (ch) __syncthreads();
#pragma unroll
        for (int it = 0; it < 2; it++) {
            int i = tid + it * 512;
            int n = i >> 3;
            int q = (i & 7) * 4;
            int gw = n * 64 + ch * 32 + q;
            *(uint4*)&sBhi[n * S2 + q] = *(const uint4*)&W1hi[gw];
            *(uint4*)&sBlo[n * S2 + q] = *(const uint4*)&W1lo[gw];
        }
        __syncthreads();
#pragma unroll
        for (int ks = 0; ks < 4; ks++) {
            const int kb = ks * 8;
            uint32_t aH[2][4];
#pragma unroll
            for (int mt = 0; mt < 2; mt++) {
                int base = (wm * 32 + mt * 16 + grp) * S2F + ch * 32 + kb + tig;
                aH[mt][0] = sA[base];
                aH[mt][1] = sA[base + 8 * S2F];
                aH[mt][2] = sA[base + 4];
                aH[mt][3] = sA[base + 8 * S2F + 4];
            }
#pragma unroll
            for (int nt = 0; nt < 4; nt++) {
                int bb = (wn * 32 + nt * 8 + grp) * S2 + kb + tig;
                uint32_t bh0 = sBhi[bb], bh1 = sBhi[bb + 4];
                uint32_t bl0 = sBlo[bb], bl1 = sBlo[bb + 4];
#pragma unroll
                for (int mt = 0; mt < 2; mt++) {
                    mma_f16(acc[mt][nt], aH[mt], bh0, bh1);
                    mma_f16(acc[mt][nt], aH[mt], bl0, bl1);
                }
            }
        }
    }
    __syncthreads();

    // hidden = relu(acc + b1) -> overwrite sA
#pragma unroll
    for (int mt = 0; mt < 2; mt++) {
        int lr = wm * 32 + mt * 16 + grp;
#pragma unroll
        for (int nt = 0; nt < 4; nt++) {
            int col = wn * 32 + nt * 8 + 2 * tig;
            float b0 = sB1[col], bq = sB1[col + 1];
            float v0 = fmaxf(acc[mt][nt][0] + b0, 0.f);
            float v1 = fmaxf(acc[mt][nt][1] + bq, 0.f);
            float v2 = fmaxf(acc[mt][nt][2] + b0, 0.f);
            float v3 = fmaxf(acc[mt][nt][3] + bq, 0.f);
            sA[lr * S2F + (col >> 1)]       = pack2(__float2half_rn(v0), __float2half_rn(v1));
            sA[(lr + 8) * S2F + (col >> 1)] = pack2(__float2half_rn(v2), __float2half_rn(v3));
            acc[mt][nt][0] = 0.f; acc[mt][nt][1] = 0.f;
            acc[mt][nt][2] = 0.f; acc[mt][nt][3] = 0.f;
        }
    }

    // ================= GEMM 2 =================
    for (int ch = 0; ch < 2; ch++) {
        if (ch) __syncthreads();
#pragma unroll
        for (int it = 0; it < 2; it++) {
            int i = tid + it * 512;
            int n = i >> 3;
            int q = (i & 7) * 4;
            int gw = n * 64 + ch * 32 + q;
            *(uint4*)&sBhi[n * S2 + q] = *(const uint4*)&W2hi[gw];
            *(uint4*)&sBlo[n * S2 + q] = *(const uint4*)&W2lo[gw];
        }
        __syncthreads();
#pragma unroll
        for (int ks = 0; ks < 4; ks++) {
            const int kb = ks * 8;
            uint32_t aH[2][4];
#pragma unroll
            for (int mt = 0; mt < 2; mt++) {
                int base = (wm * 32 + mt * 16 + grp) * S2F + ch * 32 + kb + tig;
                aH[mt][0] = sA[base];
                aH[mt][1] = sA[base + 8 * S2F];
                aH[mt][2] = sA[base + 4];
                aH[mt][3] = sA[base + 8 * S2F + 4];
            }
#pragma unroll
            for (int nt = 0; nt < 4; nt++) {
                int bb = (wn * 32 + nt * 8 + grp) * S2 + kb + tig;
                uint32_t bh0 = sBhi[bb], bh1 = sBhi[bb + 4];
                uint32_t bl0 = sBlo[bb], bl1 = sBlo[bb + 4];
#pragma unroll
                for (int mt = 0; mt < 2; mt++) {
                    mma_f16(acc[mt][nt], aH[mt], bh0, bh1);
                    mma_f16(acc[mt][nt], aH[mt], bl0, bl1);
                }
            }
        }
    }

    // epilogue: relu(acc + b2) * invs -> xs16
#pragma unroll
    for (int mt = 0; mt < 2; mt++) {
        int ra = row0 + wm * 32 + mt * 16 + grp;
        int rb = ra + 8;
        float sa = (ra < M) ? g_invs[ra] : 0.f;
        float sb = (rb < M) ? g_invs[rb] : 0.f;
#pragma unroll
        for (int nt = 0; nt < 4; nt++) {
            int col = wn * 32 + nt * 8 + 2 * tig;
            float b0 = sB2[col], bq = sB2[col + 1];
            float v0 = fmaxf(acc[mt][nt][0] + b0, 0.f) * sa;
            float v1 = fmaxf(acc[mt][nt][1] + bq, 0.f) * sa;
            float v2 = fmaxf(acc[mt][nt][2] + b0, 0.f) * sb;
            float v3 = fmaxf(acc[mt][nt][3] + bq, 0.f) * sb;
            __half2 pa2 = __floats2half2_rn(v0, v1);
            __half2 pb2 = __floats2half2_rn(v2, v3);
            if (ra < M) C16[(size_t)ra * 64 + (col >> 1)] = *(uint32_t*)&pa2;
            if (rb < M) C16[(size_t)rb * 64 + (col >> 1)] = *(uint32_t*)&pb2;
        }
    }
}
#define SM_MLP ((128 * S2F + 2 * TILEW) * 4 + 256 * 4)

// ---------------- fused CSR gather (fp16) + skip + LayerNorm (fp16 h) ----------------
// 8-deep unrolled gather for higher memory-level parallelism.
__global__ __launch_bounds__(256)
void k_gln(const uint32_t* __restrict__ xs16, uint32_t* __restrict__ h16,
           const float* __restrict__ scale, const float* __restrict__ offset) {
    int node = (blockIdx.x * blockDim.x + threadIdx.x) >> 5;
    int lane = threadIdx.x & 31;
    if (node >= N_NODES) return;
    const int c = lane * 4;
    const int w = lane * 2;

    float4 acc;
    {
        uint2 sv = *(const uint2*)&xs16[(size_t)node * 64 + w];
        float2 f0 = __half22float2(*(__half2*)&sv.x);
        float2 f1 = __half22float2(*(__half2*)&sv.y);
        acc = make_float4(f0.x, f0.y, f1.x, f1.y);
    }
    const int beg = g_start[node];
    const int end = beg + g_cr[node];

    for (int base = beg; base < end; base += 32) {
        int idx = (base + lane < end) ? g_csr[base + lane] : 0;
        int m = min(32, end - base);
        int j = 0;
        for (; j + 8 <= m; j += 8) {
            uint2 v[8];
#pragma unroll
            for (int q = 0; q < 8; q++) {
                int s = __shfl_sync(0xffffffffu, idx, j + q);
                v[q] = *(const uint2*)&xs16[(size_t)s * 64 + w];
            }
#pragma unroll
            for (int q = 0; q < 8; q++) {
                float2 e0 = __half22float2(*(__half2*)&v[q].x);
                float2 e1 = __half22float2(*(__half2*)&v[q].y);
                acc.x += e0.x; acc.y += e0.y; acc.z += e1.x; acc.w += e1.y;
            }
        }
        for (; j < m; j++) {
            int s = __shfl_sync(0xffffffffu, idx, j);
            uint2 v = *(const uint2*)&xs16[(size_t)s * 64 + w];
            float2 f0 = __half22float2(*(__half2*)&v.x);
            float2 f1 = __half22float2(*(__half2*)&v.y);
            acc.x += f0.x; acc.y += f0.y; acc.z += f1.x; acc.w += f1.y;
        }
    }

    float ir = g_invr[node];
    float4 vh;
    {
        uint2 hv = *(const uint2*)&h16[(size_t)node * 64 + w];
        float2 f0 = __half22float2(*(__half2*)&hv.x);
        float2 f1 = __half22float2(*(__half2*)&hv.y);
        vh = make_float4(f0.x, f0.y, f1.x, f1.y);
    }
    float4 y;
    y.x = acc.x * ir + vh.x; y.y = acc.y * ir + vh.y;
    y.z = acc.z * ir + vh.z; y.w = acc.w * ir + vh.w;

    float sum = y.x + y.y + y.z + y.w;
    float sq  = y.x * y.x + y.y * y.y + y.z * y.z + y.w * y.w;
#pragma unroll
    for (int o = 16; o; o >>= 1) {
        sum += __shfl_xor_sync(0xffffffffu, sum, o);
        sq  += __shfl_xor_sync(0xffffffffu, sq, o);
    }
    float mean = sum * (1.f / 128.f);
    float var  = sq * (1.f / 128.f) - mean * mean;
    float rs = rsqrtf(var + LN_EPS);
    float4 scv = *(const float4*)&scale[c];
    float4 ofv = *(const float4*)&offset[c];
    y.x = (y.x - mean) * rs * scv.x + ofv.x;
    y.y = (y.y - mean) * rs * scv.y + ofv.y;
    y.z = (y.z - mean) * rs * scv.z + ofv.z;
    y.w = (y.w - mean) * rs * scv.w + ofv.w;
    __half2 p0 = __floats2half2_rn(y.x, y.y);
    __half2 p1 = __floats2half2_rn(y.z, y.w);
    *(uint2*)&h16[(size_t)node * 64 + w] = make_uint2(*(uint32_t*)&p0, *(uint32_t*)&p1);
}

// ---------------- pool (fp16 h) + decode ----------------
__global__ __launch_bounds__(64)
void k_pool(const uint32_t* __restrict__ h16, const float* __restrict__ dec_w,
            const float* __restrict__ dec_b, float* __restrict__ out) {
    int g = blockIdx.x;
    int w = threadIdx.x;
    const int per = N_NODES / N_GRAPH;
    const uint32_t* base = h16 + (size_t)g * per * 64;
    float s0 = 0.f, s1 = 0.f;
#pragma unroll 8
    for (int r = 0; r < per; r++) {
        uint32_t v = base[(size_t)r * 64 + w];
        float2 f = __half22float2(*(__half2*)&v);
        s0 += f.x; s1 += f.y;
    }
    float val = (s0 * dec_w[2 * w] + s1 * dec_w[2 * w + 1]) * (1.f / (float)per);
    __shared__ float red[2];
#pragma unroll
    for (int o = 16; o; o >>= 1) val += __shfl_xor_sync(0xffffffffu, val, o);
    if ((threadIdx.x & 31) == 0) red[threadIdx.x >> 5] = val;
    __syncthreads();
    if (threadIdx.x == 0) out[g] = red[0] + red[1] + dec_b[0];
}

// ---------------- launch ----------------
extern "C" void kernel_launch(void* const* d_in, const int* in_sizes, int n_in,
                              void* d_out, int out_size) {
    const float* nodes     = (const float*)d_in[0];
    const int*   senders   = (const int*)d_in[1];
    const int*   receivers = (const int*)d_in[2];
    const float* embed_w   = (const float*)d_in[4];
    const float* embed_b   = (const float*)d_in[5];
    const float* mlp_w     = (const float*)d_in[6];
    const float* mlp_b     = (const float*)d_in[7];
    const float* ln_scale  = (const float*)d_in[8];
    const float* ln_offset = (const float*)d_in[9];
    const float* dec_w     = (const float*)d_in[10];
    const float* dec_b     = (const float*)d_in[11];
    float* out = (float*)d_out;

    uint32_t *ph16, *px16, *pwhi, *pwlo;
    cudaGetSymbolAddress((void**)&ph16, g_h16);
    cudaGetSymbolAddress((void**)&px16, g_x16);
    cudaGetSymbolAddress((void**)&pwhi, g_whi);
    cudaGetSymbolAddress((void**)&pwlo, g_wlo);

    cudaFuncSetAttribute(k_embed, cudaFuncAttributeMaxDynamicSharedMemorySize, SM_EMBED);
    cudaFuncSetAttribute(k_mlp,   cudaFuncAttributeMaxDynamicSharedMemorySize, SM_MLP);

    static cudaStream_t s2 = nullptr;
    static cudaEvent_t evFork = nullptr, evInv = nullptr, evJoin = nullptr;
    if (!s2) {
        cudaStreamCreateWithFlags(&s2, cudaStreamNonBlocking);
        cudaEventCreateWithFlags(&evFork, cudaEventDisableTiming);
        cudaEventCreateWithFlags(&evInv, cudaEventDisableTiming);
        cudaEventCreateWithFlags(&evJoin, cudaEventDisableTiming);
    }

    // ---- fork: CSR build on s2 ----
    cudaEventRecord(evFork, 0);
    cudaStreamWaitEvent(s2, evFork, 0);
    k_zero_deg<<<(N_NODES + 255) / 256, 256, 0, s2>>>();
    k_count<<<(N_EDGES + 255) / 256, 256, 0, s2>>>(senders, receivers);
    k_inv<<<(N_NODES + 255) / 256, 256, 0, s2>>>();
    cudaEventRecord(evInv, s2);
    k_fill<<<(N_EDGES + 255) / 256, 256, 0, s2>>>(senders, receivers);
    cudaEventRecord(evJoin, s2);

    const int gemm_grid = (N_NODES + 127) / 128;

    k_wconv<<<(WCONV_WORDS + 255) / 256, 256>>>(embed_w, mlp_w);
    k_embed<<<gemm_grid, 512, SM_EMBED>>>(nodes, pwhi, pwlo, embed_b, ph16, N_NODES);

    const uint32_t* whi_mlp[4];
    const uint32_t* wlo_mlp[4];
    for (int g = 0; g < 4; g++) {
        whi_mlp[g] = pwhi + 4096 + g * 8192;
        wlo_mlp[g] = pwlo + 4096 + g * 8192;
    }

    const int row_grid = (N_NODES * 32 + 255) / 256;

    cudaStreamWaitEvent(0, evInv, 0);

    for (int s = 0; s < 2; s++) {
        const float* b0 = mlp_b + (size_t)(s * 2 + 0) * LATENT;
        const float* b1 = mlp_b + (size_t)(s * 2 + 1) * LATENT;

        k_mlp<<<gemm_grid, 512, SM_MLP>>>(ph16,
                                          whi_mlp[s * 2], wlo_mlp[s * 2],
                                          whi_mlp[s * 2 + 1], wlo_mlp[s * 2 + 1],
                                          b0, b1, px16, N_NODES);
        if (s == 0) cudaStreamWaitEvent(0, evJoin, 0);
        k_gln<<<row_grid, 256>>>(px16, ph16, ln_scale + s * LATENT, ln_offset + s * LATENT);
    }

    k_pool<<<N_GRAPH, 64>>>(ph16, dec_w, dec_b, out);
}

// round 13
// speedup vs baseline: 1.0491x; 1.0147x over previous
#include <cuda_runtime.h>
#include <cuda_fp16.h>
#include <cstdint>

#define N_NODES 100000
#define N_EDGES 1600000
#define N_GRAPH 100
#define IN_DIM 64
#define LATENT 128
#define LN_EPS 1e-5f

// ---------------- scratch (device globals; no allocation allowed) ----------------
__device__ uint32_t g_h16[(size_t)N_NODES * 64];     // node state, packed half2
__device__ uint32_t g_x16[(size_t)N_NODES * 64];     // xs, packed half2
__device__ int   g_cs[N_NODES];
__device__ int   g_cr[N_NODES];
__device__ float g_invs[N_NODES];
__device__ float g_invr[N_NODES];
__device__ int   g_start[N_NODES];
__device__ int   g_fill[N_NODES];
__device__ int   g_csr[N_EDGES];
__device__ int   g_cursor;
#define WCONV_WORDS (4096 + 4 * 8192)
__device__ uint32_t g_whi[WCONV_WORDS];
__device__ uint32_t g_wlo[WCONV_WORDS];

// ---------------- degree / CSR kernels ----------------
__global__ void k_zero_deg() {
    int i = blockIdx.x * blockDim.x + threadIdx.x;
    if (i < N_NODES) { g_cs[i] = 0; g_cr[i] = 0; }
    if (i == 0) g_cursor = 0;
}
__global__ void k_count(const int* __restrict__ senders, const int* __restrict__ receivers) {
    int e = blockIdx.x * blockDim.x + threadIdx.x;
    if (e < N_EDGES) {
        atomicAdd(&g_cs[senders[e]], 1);
        atomicAdd(&g_cr[receivers[e]], 1);
    }
}
__global__ void k_inv() {
    int i = blockIdx.x * blockDim.x + threadIdx.x;
    if (i < N_NODES) {
        g_invs[i] = rsqrtf((float)(g_cs[i] + 1));
        g_invr[i] = rsqrtf((float)(g_cr[i] + 1));
        int st = atomicAdd(&g_cursor, g_cr[i]);
        g_start[i] = st;
        g_fill[i] = st;
    }
}
__global__ void k_fill(const int* __restrict__ senders, const int* __restrict__ receivers) {
    int e = blockIdx.x * blockDim.x + threadIdx.x;
    if (e < N_EDGES) {
        int r = receivers[e];
        int pos = atomicAdd(&g_fill[r], 1);
        g_csr[pos] = senders[e];
    }
}

// ---------------- fp16 helpers ----------------
__device__ __forceinline__ void hilo(float x, __half& h, float& res) {
    h = __float2half_rn(x);
    res = x - __half2float(h);
}
__device__ __forceinline__ uint32_t pack2(__half a, __half b) {
    __half2 h = __halves2half2(a, b);
    return *(uint32_t*)&h;
}
__device__ __forceinline__ void mma_f16(float c[4], const uint32_t a[4],
                                        uint32_t b0, uint32_t b1) {
    asm volatile(
        "mma.sync.aligned.m16n8k16.row.col.f32.f16.f16.f32 "
        "{%0,%1,%2,%3}, {%4,%5,%6,%7}, {%8,%9}, {%0,%1,%2,%3};"
        : "+f"(c[0]), "+f"(c[1]), "+f"(c[2]), "+f"(c[3])
        : "r"(a[0]), "r"(a[1]), "r"(a[2]), "r"(a[3]),
          "r"(b0), "r"(b1));
}

// ---------------- weight pre-conversion ----------------
__global__ void k_wconv(const float* __restrict__ embed_w, const float* __restrict__ mlp_w) {
    int i = blockIdx.x * blockDim.x + threadIdx.x;
    if (i >= WCONV_WORDS) return;
    float v0, v1;
    if (i < 4096) {
        int n = i >> 5, kp = i & 31;
        v0 = embed_w[(size_t)(2 * kp) * 128 + n];
        v1 = embed_w[(size_t)(2 * kp + 1) * 128 + n];
    } else {
        int j = i - 4096;
        int g = j >> 13;
        int r = j & 8191;
        int n = r >> 6, kp = r & 63;
        const float* W = mlp_w + (size_t)g * 128 * 128;
        v0 = W[(size_t)(2 * kp) * 128 + n];
        v1 = W[(size_t)(2 * kp + 1) * 128 + n];
    }
    __half h0, h1; float r0, r1;
    hilo(v0, h0, r0); hilo(v1, h1, r1);
    g_whi[i] = pack2(h0, h1);
    g_wlo[i] = pack2(__float2half_rn(r0), __float2half_rn(r1));
}

#define S2  36    // B chunk stride (words)
#define S2F 68    // A full-K stride (words)
#define TILEW (128 * S2)

// ---------------- embed GEMM: fp32 A, hi/lo split (3 passes), K=64 ----------------
__global__ __launch_bounds__(512, 2)
void k_embed(const float* __restrict__ A,
             const uint32_t* __restrict__ Whi, const uint32_t* __restrict__ Wlo,
             const float* __restrict__ bias, uint32_t* __restrict__ C16, int M) {
    extern __shared__ uint32_t sm[];
    uint32_t* sAhi = sm;
    uint32_t* sBhi = sm + TILEW;
    uint32_t* sBlo = sm + 2 * TILEW;
    uint32_t* sAlo = sm + 3 * TILEW;
    float*    sBias = (float*)(sm + 4 * TILEW);

    const int tid  = threadIdx.x;
    const int lane = tid & 31;
    const int wid  = tid >> 5;
    const int grp  = lane >> 2;
    const int tig  = lane & 3;
    const int wm   = wid & 3;
    const int wn   = wid >> 2;
    const int row0 = blockIdx.x * 128;

    if (tid < 128) sBias[tid] = bias[tid];

    float acc[2][4][4];
#pragma unroll
    for (int i = 0; i < 2; i++)
#pragma unroll
        for (int j = 0; j < 4; j++)
#pragma unroll
            for (int q = 0; q < 4; q++) acc[i][j][q] = 0.f;

    // stage A [128 x 64] fp32 -> fp16 hi/lo
#pragma unroll
    for (int it = 0; it < 4; it++) {
        int i  = tid + it * 512;
        int r  = i >> 4;
        int c4 = (i & 15) * 4;
        float4 v = make_float4(0.f, 0.f, 0.f, 0.f);
        if (row0 + r < M)
            v = *(const float4*)&A[(size_t)(row0 + r) * 64 + c4];
        __half h0, h1, h2, h3; float r0, r1, r2, r3;
        hilo(v.x, h0, r0); hilo(v.y, h1, r1);
        hilo(v.z, h2, r2); hilo(v.w, h3, r3);
        int w = r * S2 + (c4 >> 1);
        *(uint2*)&sAhi[w] = make_uint2(pack2(h0, h1), pack2(h2, h3));
        *(uint2*)&sAlo[w] = make_uint2(
            pack2(__float2half_rn(r0), __float2half_rn(r1)),
            pack2(__float2half_rn(r2), __float2half_rn(r3)));
    }
    // stage B [128 n x 32 kp]
#pragma unroll
    for (int it = 0; it < 2; it++) {
        int i = tid + it * 512;
        int n = i >> 3;
        int q = (i & 7) * 4;
        if (q < 32) {
            *(uint4*)&sBhi[n * S2 + q] = *(const uint4*)&Whi[n * 32 + q];
            *(uint4*)&sBlo[n * S2 + q] = *(const uint4*)&Wlo[n * 32 + q];
        }
    }
    __syncthreads();

#pragma unroll
    for (int ks = 0; ks < 4; ks++) {
        const int kb = ks * 8;
        uint32_t aH[2][4], aL[2][4];
#pragma unroll
        for (int mt = 0; mt < 2; mt++) {
            int base = (wm * 32 + mt * 16 + grp) * S2 + kb + tig;
            aH[mt][0] = sAhi[base];
            aH[mt][1] = sAhi[base + 8 * S2];
            aH[mt][2] = sAhi[base + 4];
            aH[mt][3] = sAhi[base + 8 * S2 + 4];
            aL[mt][0] = sAlo[base];
            aL[mt][1] = sAlo[base + 8 * S2];
            aL[mt][2] = sAlo[base + 4];
            aL[mt][3] = sAlo[base + 8 * S2 + 4];
        }
#pragma unroll
        for (int nt = 0; nt < 4; nt++) {
            int bb = (wn * 32 + nt * 8 + grp) * S2 + kb + tig;
            uint32_t bh0 = sBhi[bb], bh1 = sBhi[bb + 4];
            uint32_t bl0 = sBlo[bb], bl1 = sBlo[bb + 4];
#pragma unroll
            for (int mt = 0; mt < 2; mt++) {
                mma_f16(acc[mt][nt], aH[mt], bh0, bh1);
                mma_f16(acc[mt][nt], aH[mt], bl0, bl1);
                mma_f16(acc[mt][nt], aL[mt], bh0, bh1);
            }
        }
    }

#pragma unroll
    for (int mt = 0; mt < 2; mt++) {
        int ra = row0 + wm * 32 + mt * 16 + grp;
        int rb = ra + 8;
#pragma unroll
        for (int nt = 0; nt < 4; nt++) {
            int col = wn * 32 + nt * 8 + 2 * tig;
            float b0 = sBias[col], b1 = sBias[col + 1];
            __half2 pa2 = __floats2half2_rn(acc[mt][nt][0] + b0, acc[mt][nt][1] + b1);
            __half2 pb2 = __floats2half2_rn(acc[mt][nt][2] + b0, acc[mt][nt][3] + b1);
            if (ra < M) C16[(size_t)ra * 64 + (col >> 1)] = *(uint32_t*)&pa2;
            if (rb < M) C16[(size_t)rb * 64 + (col >> 1)] = *(uint32_t*)&pb2;
        }
    }
}
#define SM_EMBED (4 * TILEW * 4 + 128 * 4)

// ---------------- fused 2-layer MLP: xs = relu(relu(h@W1+b1)@W2+b2) * invs ----------------
__global__ __launch_bounds__(512, 2)
void k_mlp(const uint32_t* __restrict__ A16,
           const uint32_t* __restrict__ W1hi, const uint32_t* __restrict__ W1lo,
           const uint32_t* __restrict__ W2hi, const uint32_t* __restrict__ W2lo,
           const float* __restrict__ b1, const float* __restrict__ b2,
           uint32_t* __restrict__ C16, int M) {
    extern __shared__ uint32_t sm[];
    uint32_t* sA   = sm;                       // 128 x S2F (full K, fp16 words)
    uint32_t* sBhi = sm + 128 * S2F;
    uint32_t* sBlo = sBhi + TILEW;
    float*    sB1  = (float*)(sBlo + TILEW);
    float*    sB2  = sB1 + 128;

    const int tid  = threadIdx.x;
    const int lane = tid & 31;
    const int wid  = tid >> 5;
    const int grp  = lane >> 2;
    const int tig  = lane & 3;
    const int wm   = wid & 3;
    const int wn   = wid >> 2;
    const int row0 = blockIdx.x * 128;

    if (tid < 128) { sB1[tid] = b1[tid]; sB2[tid] = b2[tid]; }

    // stage A full-K [128 rows x 64 words]
#pragma unroll
    for (int it = 0; it < 4; it++) {
        int i = tid + it * 512;
        int r = i >> 4;
        int q = (i & 15) * 4;
        uint4 v = make_uint4(0, 0, 0, 0);
        if (row0 + r < M)
            v = *(const uint4*)&A16[(size_t)(row0 + r) * 64 + q];
        *(uint4*)&sA[r * S2F + q] = v;
    }

    float acc[2][4][4];
#pragma unroll
    for (int i = 0; i < 2; i++)
#pragma unroll
        for (int j = 0; j < 4; j++)
#pragma unroll
            for (int q = 0; q < 4; q++) acc[i][j][q] = 0.f;

    // ================= GEMM 1 =================
    for (int ch = 0; ch < 2; ch++) {
        if (ch) __syncthreads();
#pragma unroll
        for (int it = 0; it < 2; it++) {
            int i = tid + it * 512;
            int n = i >> 3;
            int q = (i & 7) * 4;
            int gw = n * 64 + ch * 32 + q;
            *(uint4*)&sBhi[n * S2 + q] = *(const uint4*)&W1hi[gw];
            *(uint4*)&sBlo[n * S2 + q] = *(const uint4*)&W1lo[gw];
        }
        __syncthreads();
#pragma unroll
        for (int ks = 0; ks < 4; ks++) {
            const int kb = ks * 8;
            uint32_t aH[2][4];
#pragma unroll
            for (int mt = 0; mt < 2; mt++) {
                int base = (wm * 32 + mt * 16 + grp) * S2F + ch * 32 + kb + tig;
                aH[mt][0] = sA[base];
                aH[mt][1] = sA[base + 8 * S2F];
                aH[mt][2] = sA[base + 4];
                aH[mt][3] = sA[base + 8 * S2F + 4];
            }
#pragma unroll
            for (int nt = 0; nt < 4; nt++) {
                int bb = (wn * 32 + nt * 8 + grp) * S2 + kb + tig;
                uint32_t bh0 = sBhi[bb], bh1 = sBhi[bb + 4];
                uint32_t bl0 = sBlo[bb], bl1 = sBlo[bb + 4];
#pragma unroll
                for (int mt = 0; mt < 2; mt++) {
                    mma_f16(acc[mt][nt], aH[mt], bh0, bh1);
                    mma_f16(acc[mt][nt], aH[mt], bl0, bl1);
                }
            }
        }
    }
    __syncthreads();

    // hidden = relu(acc + b1) -> overwrite sA
#pragma unroll
    for (int mt = 0; mt < 2; mt++) {
        int lr = wm * 32 + mt * 16 + grp;
#pragma unroll
        for (int nt = 0; nt < 4; nt++) {
            int col = wn * 32 + nt * 8 + 2 * tig;
            float b0 = sB1[col], bq = sB1[col + 1];
            float v0 = fmaxf(acc[mt][nt][0] + b0, 0.f);
            float v1 = fmaxf(acc[mt][nt][1] + bq, 0.f);
            float v2 = fmaxf(acc[mt][nt][2] + b0, 0.f);
            float v3 = fmaxf(acc[mt][nt][3] + bq, 0.f);
            sA[lr * S2F + (col >> 1)]       = pack2(__float2half_rn(v0), __float2half_rn(v1));
            sA[(lr + 8) * S2F + (col >> 1)] = pack2(__float2half_rn(v2), __float2half_rn(v3));
            acc[mt][nt][0] = 0.f; acc[mt][nt][1] = 0.f;
            acc[mt][nt][2] = 0.f; acc[mt][nt][3] = 0.f;
        }
    }

    // ================= GEMM 2 =================
    for (int ch = 0; ch < 2; ch++) {
        if (ch) __syncthreads();
#pragma unroll
        for (int it = 0; it < 2; it++) {
            int i = tid + it * 512;
            int n = i >> 3;
            int q = (i & 7) * 4;
            int gw = n * 64 + ch * 32 + q;
            *(uint4*)&sBhi[n * S2 + q] = *(const uint4*)&W2hi[gw];
            *(uint4*)&sBlo[n * S2 + q] = *(const uint4*)&W2lo[gw];
        }
        __syncthreads();
#pragma unroll
        for (int ks = 0; ks < 4; ks++) {
            const int kb = ks * 8;
            uint32_t aH[2][4];
#pragma unroll
            for (int mt = 0; mt < 2; mt++) {
                int base = (wm * 32 + mt * 16 + grp) * S2F + ch * 32 + kb + tig;
                aH[mt][0] = sA[base];
                aH[mt][1] = sA[base + 8 * S2F];
                aH[mt][2] = sA[base + 4];
                aH[mt][3] = sA[base + 8 * S2F + 4];
            }
#pragma unroll
            for (int nt = 0; nt < 4; nt++) {
                int bb = (wn * 32 + nt * 8 + grp) * S2 + kb + tig;
                uint32_t bh0 = sBhi[bb], bh1 = sBhi[bb + 4];
                uint32_t bl0 = sBlo[bb], bl1 = sBlo[bb + 4];
#pragma unroll
                for (int mt = 0; mt < 2; mt++) {
                    mma_f16(acc[mt][nt], aH[mt], bh0, bh1);
                    mma_f16(acc[mt][nt], aH[mt], bl0, bl1);
                }
            }
        }
    }

    // epilogue: relu(acc + b2) * invs -> xs16
#pragma unroll
    for (int mt = 0; mt < 2; mt++) {
        int ra = row0 + wm * 32 + mt * 16 + grp;
        int rb = ra + 8;
        float sa = (ra < M) ? g_invs[ra] : 0.f;
        float sb = (rb < M) ? g_invs[rb] : 0.f;
#pragma unroll
        for (int nt = 0; nt < 4; nt++) {
            int col = wn * 32 + nt * 8 + 2 * tig;
            float b0 = sB2[col], bq = sB2[col + 1];
            float v0 = fmaxf(acc[mt][nt][0] + b0, 0.f) * sa;
            float v1 = fmaxf(acc[mt][nt][1] + bq, 0.f) * sa;
            float v2 = fmaxf(acc[mt][nt][2] + b0, 0.f) * sb;
            float v3 = fmaxf(acc[mt][nt][3] + bq, 0.f) * sb;
            __half2 pa2 = __floats2half2_rn(v0, v1);
            __half2 pb2 = __floats2half2_rn(v2, v3);
            if (ra < M) C16[(size_t)ra * 64 + (col >> 1)] = *(uint32_t*)&pa2;
            if (rb < M) C16[(size_t)rb * 64 + (col >> 1)] = *(uint32_t*)&pb2;
        }
    }
}
#define SM_MLP ((128 * S2F + 2 * TILEW) * 4 + 256 * 4)

// ---------------- fused CSR gather (fp16) + skip + LayerNorm (fp16 h) ----------------
// R10 4-deep gather; h skip-read and invr hoisted before the gather loop.
__global__ __launch_bounds__(256)
void k_gln(const uint32_t* __restrict__ xs16, uint32_t* __restrict__ h16,
           const float* __restrict__ scale, const float* __restrict__ offset) {
    int node = (blockIdx.x * blockDim.x + threadIdx.x) >> 5;
    int lane = threadIdx.x & 31;
    if (node >= N_NODES) return;
    const int c = lane * 4;
    const int w = lane * 2;

    // hoisted: skip connection + receiver norm (overlap with gather latency)
    const float ir = g_invr[node];
    const uint2 hv = *(const uint2*)&h16[(size_t)node * 64 + w];

    float4 acc;
    {
        uint2 sv = *(const uint2*)&xs16[(size_t)node * 64 + w];
        float2 f0 = __half22float2(*(__half2*)&sv.x);
        float2 f1 = __half22float2(*(__half2*)&sv.y);
        acc = make_float4(f0.x, f0.y, f1.x, f1.y);
    }
    const int beg = g_start[node];
    const int end = beg + g_cr[node];

    for (int base = beg; base < end; base += 32) {
        int idx = (base + lane < end) ? g_csr[base + lane] : 0;
        int m = min(32, end - base);
        int j = 0;
        for (; j + 4 <= m; j += 4) {
            int s0 = __shfl_sync(0xffffffffu, idx, j);
            int s1 = __shfl_sync(0xffffffffu, idx, j + 1);
            int s2 = __shfl_sync(0xffffffffu, idx, j + 2);
            int s3 = __shfl_sync(0xffffffffu, idx, j + 3);
            uint2 v0 = *(const uint2*)&xs16[(size_t)s0 * 64 + w];
            uint2 v1 = *(const uint2*)&xs16[(size_t)s1 * 64 + w];
            uint2 v2 = *(const uint2*)&xs16[(size_t)s2 * 64 + w];
            uint2 v3 = *(const uint2*)&xs16[(size_t)s3 * 64 + w];
            float2 e;
            e = __half22float2(*(__half2*)&v0.x); acc.x += e.x; acc.y += e.y;
            e = __half22float2(*(__half2*)&v1.x); acc.x += e.x; acc.y += e.y;
            e = __half22float2(*(__half2*)&v2.x); acc.x += e.x; acc.y += e.y;
            e = __half22float2(*(__half2*)&v3.x); acc.x += e.x; acc.y += e.y;
            e = __half22float2(*(__half2*)&v0.y); acc.z += e.x; acc.w += e.y;
            e = __half22float2(*(__half2*)&v1.y); acc.z += e.x; acc.w += e.y;
            e = __half22float2(*(__half2*)&v2.y); acc.z += e.x; acc.w += e.y;
            e = __half22float2(*(__half2*)&v3.y); acc.z += e.x; acc.w += e.y;
        }
        for (; j < m; j++) {
            int s = __shfl_sync(0xffffffffu, idx, j);
            uint2 v = *(const uint2*)&xs16[(size_t)s * 64 + w];
            float2 f0 = __half22float2(*(__half2*)&v.x);
            float2 f1 = __half22float2(*(__half2*)&v.y);
            acc.x += f0.x; acc.y += f0.y; acc.z += f1.x; acc.w += f1.y;
        }
    }

    float4 vh;
    {
        float2 f0 = __half22float2(*(__half2*)&hv.x);
        float2 f1 = __half22float2(*(__half2*)&hv.y);
        vh = make_float4(f0.x, f0.y, f1.x, f1.y);
    }
    float4 y;
    y.x = acc.x * ir + vh.x; y.y = acc.y * ir + vh.y;
    y.z = acc.z * ir + vh.z; y.w = acc.w * ir + vh.w;

    float sum = y.x + y.y + y.z + y.w;
    float sq  = y.x * y.x + y.y * y.y + y.z * y.z + y.w * y.w;
#pragma unroll
    for (int o = 16; o; o >>= 1) {
        sum += __shfl_xor_sync(0xffffffffu, sum, o);
        sq  += __shfl_xor_sync(0xffffffffu, sq, o);
    }
    float mean = sum * (1.f / 128.f);
    float var  = sq * (1.f / 128.f) - mean * mean;
    float rs = rsqrtf(var + LN_EPS);
    float4 scv = *(const float4*)&scale[c];
    float4 ofv = *(const float4*)&offset[c];
    y.x = (y.x - mean) * rs * scv.x + ofv.x;
    y.y = (y.y - mean) * rs * scv.y + ofv.y;
    y.z = (y.z - mean) * rs * scv.z + ofv.z;
    y.w = (y.w - mean) * rs * scv.w + ofv.w;
    __half2 p0 = __floats2half2_rn(y.x, y.y);
    __half2 p1 = __floats2half2_rn(y.z, y.w);
    *(uint2*)&h16[(size_t)node * 64 + w] = make_uint2(*(uint32_t*)&p0, *(uint32_t*)&p1);
}

// ---------------- pool (fp16 h) + decode ----------------
__global__ __launch_bounds__(64)
void k_pool(const uint32_t* __restrict__ h16, const float* __restrict__ dec_w,
            const float* __restrict__ dec_b, float* __restrict__ out) {
    int g = blockIdx.x;
    int w = threadIdx.x;
    const int per = N_NODES / N_GRAPH;
    const uint32_t* base = h16 + (size_t)g * per * 64;
    float s0 = 0.f, s1 = 0.f;
#pragma unroll 8
    for (int r = 0; r < per; r++) {
        uint32_t v = base[(size_t)r * 64 + w];
        float2 f = __half22float2(*(__half2*)&v);
        s0 += f.x; s1 += f.y;
    }
    float val = (s0 * dec_w[2 * w] + s1 * dec_w[2 * w + 1]) * (1.f / (float)per);
    __shared__ float red[2];
#pragma unroll
    for (int o = 16; o; o >>= 1) val += __shfl_xor_sync(0xffffffffu, val, o);
    if ((threadIdx.x & 31) == 0) red[threadIdx.x >> 5] = val;
    __syncthreads();
    if (threadIdx.x == 0) out[g] = red[0] + red[1] + dec_b[0];
}

// ---------------- launch ----------------
extern "C" void kernel_launch(void* const* d_in, const int* in_sizes, int n_in,
                              void* d_out, int out_size) {
    const float* nodes     = (const float*)d_in[0];
    const int*   senders   = (const int*)d_in[1];
    const int*   receivers = (const int*)d_in[2];
    const float* embed_w   = (const float*)d_in[4];
    const float* embed_b   = (const float*)d_in[5];
    const float* mlp_w     = (const float*)d_in[6];
    const float* mlp_b     = (const float*)d_in[7];
    const float* ln_scale  = (const float*)d_in[8];
    const float* ln_offset = (const float*)d_in[9];
    const float* dec_w     = (const float*)d_in[10];
    const float* dec_b     = (const float*)d_in[11];
    float* out = (float*)d_out;

    uint32_t *ph16, *px16, *pwhi, *pwlo;
    cudaGetSymbolAddress((void**)&ph16, g_h16);
    cudaGetSymbolAddress((void**)&px16, g_x16);
    cudaGetSymbolAddress((void**)&pwhi, g_whi);
    cudaGetSymbolAddress((void**)&pwlo, g_wlo);

    cudaFuncSetAttribute(k_embed, cudaFuncAttributeMaxDynamicSharedMemorySize, SM_EMBED);
    cudaFuncSetAttribute(k_mlp,   cudaFuncAttributeMaxDynamicSharedMemorySize, SM_MLP);

    static cudaStream_t s2 = nullptr;
    static cudaEvent_t evFork = nullptr, evInv = nullptr, evJoin = nullptr;
    if (!s2) {
        cudaStreamCreateWithFlags(&s2, cudaStreamNonBlocking);
        cudaEventCreateWithFlags(&evFork, cudaEventDisableTiming);
        cudaEventCreateWithFlags(&evInv, cudaEventDisableTiming);
        cudaEventCreateWithFlags(&evJoin, cudaEventDisableTiming);
    }

    // ---- fork: CSR build on s2 ----
    cudaEventRecord(evFork, 0);
    cudaStreamWaitEvent(s2, evFork, 0);
    k_zero_deg<<<(N_NODES + 255) / 256, 256, 0, s2>>>();
    k_count<<<(N_EDGES + 255) / 256, 256, 0, s2>>>(senders, receivers);
    k_inv<<<(N_NODES + 255) / 256, 256, 0, s2>>>();
    cudaEventRecord(evInv, s2);
    k_fill<<<(N_EDGES + 255) / 256, 256, 0, s2>>>(senders, receivers);
    cudaEventRecord(evJoin, s2);

    const int gemm_grid = (N_NODES + 127) / 128;

    k_wconv<<<(WCONV_WORDS + 255) / 256, 256>>>(embed_w, mlp_w);
    k_embed<<<gemm_grid, 512, SM_EMBED>>>(nodes, pwhi, pwlo, embed_b, ph16, N_NODES);

    const uint32_t* whi_mlp[4];
    const uint32_t* wlo_mlp[4];
    for (int g = 0; g < 4; g++) {
        whi_mlp[g] = pwhi + 4096 + g * 8192;
        wlo_mlp[g] = pwlo + 4096 + g * 8192;
    }

    const int row_grid = (N_NODES * 32 + 255) / 256;

    cudaStreamWaitEvent(0, evInv, 0);

    for (int s = 0; s < 2; s++) {
        const float* b0 = mlp_b + (size_t)(s * 2 + 0) * LATENT;
        const float* b1 = mlp_b + (size_t)(s * 2 + 1) * LATENT;

        k_mlp<<<gemm_grid, 512, SM_MLP>>>(ph16,
                                          whi_mlp[s * 2], wlo_mlp[s * 2],
                                          whi_mlp[s * 2 + 1], wlo_mlp[s * 2 + 1],
                                          b0, b1, px16, N_NODES);
        if (s == 0) cudaStreamWaitEvent(0, evJoin, 0);
        k_gln<<<row_grid, 256>>>(px16, ph16, ln_scale + s * LATENT, ln_offset + s * LATENT);
    }

    k_pool<<<N_GRAPH, 64>>>(ph16, dec_w, dec_b, out);
}

// round 14
// speedup vs baseline: 1.0720x; 1.0218x over previous
#include <cuda_runtime.h>
#include <cuda_fp16.h>
#include <cstdint>

#define N_NODES 100000
#define N_EDGES 1600000
#define N_GRAPH 100
#define IN_DIM 64
#define LATENT 128
#define LN_EPS 1e-5f

#define PDL_TRIGGER() asm volatile("griddepcontrol.launch_dependents;" ::: "memory")
#define PDL_WAIT()    asm volatile("griddepcontrol.wait;" ::: "memory")

// ---------------- scratch (device globals; no allocation allowed) ----------------
__device__ uint32_t g_h16[(size_t)N_NODES * 64];     // node state, packed half2
__device__ uint32_t g_x16[(size_t)N_NODES * 64];     // xs, packed half2
__device__ int   g_cs[N_NODES];
__device__ int   g_cr[N_NODES];
__device__ float g_invs[N_NODES];
__device__ float g_invr[N_NODES];
__device__ int   g_start[N_NODES];
__device__ int   g_fill[N_NODES];
__device__ int   g_csr[N_EDGES];
__device__ int   g_cursor;
#define WCONV_WORDS (4096 + 4 * 8192)
__device__ uint32_t g_whi[WCONV_WORDS];
__device__ uint32_t g_wlo[WCONV_WORDS];

// ---------------- degree / CSR kernels ----------------
__global__ void k_zero_deg() {
    int i = blockIdx.x * blockDim.x + threadIdx.x;
    if (i < N_NODES) { g_cs[i] = 0; g_cr[i] = 0; }
    if (i == 0) g_cursor = 0;
}
__global__ void k_count(const int* __restrict__ senders, const int* __restrict__ receivers) {
    int e = blockIdx.x * blockDim.x + threadIdx.x;
    if (e < N_EDGES) {
        atomicAdd(&g_cs[senders[e]], 1);
        atomicAdd(&g_cr[receivers[e]], 1);
    }
}
__global__ void k_inv() {
    int i = blockIdx.x * blockDim.x + threadIdx.x;
    if (i < N_NODES) {
        g_invs[i] = rsqrtf((float)(g_cs[i] + 1));
        g_invr[i] = rsqrtf((float)(g_cr[i] + 1));
        int st = atomicAdd(&g_cursor, g_cr[i]);
        g_start[i] = st;
        g_fill[i] = st;
    }
}
__global__ void k_fill(const int* __restrict__ senders, const int* __restrict__ receivers) {
    int e = blockIdx.x * blockDim.x + threadIdx.x;
    if (e < N_EDGES) {
        int r = receivers[e];
        int pos = atomicAdd(&g_fill[r], 1);
        g_csr[pos] = senders[e];
    }
}

// ---------------- fp16 helpers ----------------
__device__ __forceinline__ void hilo(float x, __half& h, float& res) {
    h = __float2half_rn(x);
    res = x - __half2float(h);
}
__device__ __forceinline__ uint32_t pack2(__half a, __half b) {
    __half2 h = __halves2half2(a, b);
    return *(uint32_t*)&h;
}
__device__ __forceinline__ void mma_f16(float c[4], const uint32_t a[4],
                                        uint32_t b0, uint32_t b1) {
    asm volatile(
        "mma.sync.aligned.m16n8k16.row.col.f32.f16.f16.f32 "
        "{%0,%1,%2,%3}, {%4,%5,%6,%7}, {%8,%9}, {%0,%1,%2,%3};"
        : "+f"(c[0]), "+f"(c[1]), "+f"(c[2]), "+f"(c[3])
        : "r"(a[0]), "r"(a[1]), "r"(a[2]), "r"(a[3]),
          "r"(b0), "r"(b1));
}

// ---------------- weight pre-conversion ----------------
__global__ void k_wconv(const float* __restrict__ embed_w, const float* __restrict__ mlp_w) {
    int i = blockIdx.x * blockDim.x + threadIdx.x;
    if (i >= WCONV_WORDS) return;
    float v0, v1;
    if (i < 4096) {
        int n = i >> 5, kp = i & 31;
        v0 = embed_w[(size_t)(2 * kp) * 128 + n];
        v1 = embed_w[(size_t)(2 * kp + 1) * 128 + n];
    } else {
        int j = i - 4096;
        int g = j >> 13;
        int r = j & 8191;
        int n = r >> 6, kp = r & 63;
        const float* W = mlp_w + (size_t)g * 128 * 128;
        v0 = W[(size_t)(2 * kp) * 128 + n];
        v1 = W[(size_t)(2 * kp + 1) * 128 + n];
    }
    __half h0, h1; float r0, r1;
    hilo(v0, h0, r0); hilo(v1, h1, r1);
    g_whi[i] = pack2(h0, h1);
    g_wlo[i] = pack2(__float2half_rn(r0), __float2half_rn(r1));
}

#define S2  36    // B chunk stride (words)
#define S2F 68    // A full-K stride (words)
#define TILEW (128 * S2)

// ---------------- embed GEMM: fp32 A, hi/lo split (3 passes), K=64 ----------------
__global__ __launch_bounds__(512, 2)
void k_embed(const float* __restrict__ A,
             const uint32_t* __restrict__ Whi, const uint32_t* __restrict__ Wlo,
             const float* __restrict__ bias, uint32_t* __restrict__ C16, int M) {
    extern __shared__ uint32_t sm[];
    uint32_t* sAhi = sm;
    uint32_t* sBhi = sm + TILEW;
    uint32_t* sBlo = sm + 2 * TILEW;
    uint32_t* sAlo = sm + 3 * TILEW;
    float*    sBias = (float*)(sm + 4 * TILEW);

    PDL_TRIGGER();   // allow mlp0 to launch early (it waits before reading h16)

    const int tid  = threadIdx.x;
    const int lane = tid & 31;
    const int wid  = tid >> 5;
    const int grp  = lane >> 2;
    const int tig  = lane & 3;
    const int wm   = wid & 3;
    const int wn   = wid >> 2;
    const int row0 = blockIdx.x * 128;

    if (tid < 128) sBias[tid] = bias[tid];

    float acc[2][4][4];
#pragma unroll
    for (int i = 0; i < 2; i++)
#pragma unroll
        for (int j = 0; j < 4; j++)
#pragma unroll
            for (int q = 0; q < 4; q++) acc[i][j][q] = 0.f;

    // stage A [128 x 64] fp32 -> fp16 hi/lo
#pragma unroll
    for (int it = 0; it < 4; it++) {
        int i  = tid + it * 512;
        int r  = i >> 4;
        int c4 = (i & 15) * 4;
        float4 v = make_float4(0.f, 0.f, 0.f, 0.f);
        if (row0 + r < M)
            v = *(const float4*)&A[(size_t)(row0 + r) * 64 + c4];
        __half h0, h1, h2, h3; float r0, r1, r2, r3;
        hilo(v.x, h0, r0); hilo(v.y, h1, r1);
        hilo(v.z, h2, r2); hilo(v.w, h3, r3);
        int w = r * S2 + (c4 >> 1);
        *(uint2*)&sAhi[w] = make_uint2(pack2(h0, h1), pack2(h2, h3));
        *(uint2*)&sAlo[w] = make_uint2(
            pack2(__float2half_rn(r0), __float2half_rn(r1)),
            pack2(__float2half_rn(r2), __float2half_rn(r3)));
    }
    // stage B [128 n x 32 kp]
#pragma unroll
    for (int it = 0; it < 2; it++) {
        int i = tid + it * 512;
        int n = i >> 3;
        int q = (i & 7) * 4;
        if (q < 32) {
            *(uint4*)&sBhi[n * S2 + q] = *(const uint4*)&Whi[n * 32 + q];
            *(uint4*)&sBlo[n * S2 + q] = *(const uint4*)&Wlo[n * 32 + q];
        }
    }
    __syncthreads();

#pragma unroll
    for (int ks = 0; ks < 4; ks++) {
        const int kb = ks * 8;
        uint32_t aH[2][4], aL[2][4];
#pragma unroll
        for (int mt = 0; mt < 2; mt++) {
            int base = (wm * 32 + mt * 16 + grp) * S2 + kb + tig;
            aH[mt][0] = sAhi[base];
            aH[mt][1] = sAhi[base + 8 * S2];
            aH[mt][2] = sAhi[base + 4];
            aH[mt][3] = sAhi[base + 8 * S2 + 4];
            aL[mt][0] = sAlo[base];
            aL[mt][1] = sAlo[base + 8 * S2];
            aL[mt][2] = sAlo[base + 4];
            aL[mt][3] = sAlo[base + 8 * S2 + 4];
        }
#pragma unroll
        for (int nt = 0; nt < 4; nt++) {
            int bb = (wn * 32 + nt * 8 + grp) * S2 + kb + tig;
            uint32_t bh0 = sBhi[bb], bh1 = sBhi[bb + 4];
            uint32_t bl0 = sBlo[bb], bl1 = sBlo[bb + 4];
#pragma unroll
            for (int mt = 0; mt < 2; mt++) {
                mma_f16(acc[mt][nt], aH[mt], bh0, bh1);
                mma_f16(acc[mt][nt], aH[mt], bl0, bl1);
                mma_f16(acc[mt][nt], aL[mt], bh0, bh1);
            }
        }
    }

#pragma unroll
    for (int mt = 0; mt < 2; mt++) {
        int ra = row0 + wm * 32 + mt * 16 + grp;
        int rb = ra + 8;
#pragma unroll
        for (int nt = 0; nt < 4; nt++) {
            int col = wn * 32 + nt * 8 + 2 * tig;
            float b0 = sBias[col], b1 = sBias[col + 1];
            __half2 pa2 = __floats2half2_rn(acc[mt][nt][0] + b0, acc[mt][nt][1] + b1);
            __half2 pb2 = __floats2half2_rn(acc[mt][nt][2] + b0, acc[mt][nt][3] + b1);
            if (ra < M) C16[(size_t)ra * 64 + (col >> 1)] = *(uint32_t*)&pa2;
            if (rb < M) C16[(size_t)rb * 64 + (col >> 1)] = *(uint32_t*)&pb2;
        }
    }
}
#define SM_EMBED (4 * TILEW * 4 + 128 * 4)

// ---------------- fused 2-layer MLP: xs = relu(relu(h@W1+b1)@W2+b2) * invs ----------------
// PDL: trigger at entry; stage W1 chunk0 + biases pre-wait; read h16 post-wait.
__global__ __launch_bounds__(512, 2)
void k_mlp(const uint32_t* __restrict__ A16,
           const uint32_t* __restrict__ W1hi, const uint32_t* __restrict__ W1lo,
           const uint32_t* __restrict__ W2hi, const uint32_t* __restrict__ W2lo,
           const float* __restrict__ b1, const float* __restrict__ b2,
           uint32_t* __restrict__ C16, int M) {
    extern __shared__ uint32_t sm[];
    uint32_t* sA   = sm;                       // 128 x S2F (full K, fp16 words)
    uint32_t* sBhi = sm + 128 * S2F;
    uint32_t* sBlo = sBhi + TILEW;
    float*    sB1  = (float*)(sBlo + TILEW);
    float*    sB2  = sB1 + 128;

    PDL_TRIGGER();

    const int tid  = threadIdx.x;
    const int lane = tid & 31;
    const int wid  = tid >> 5;
    const int grp  = lane >> 2;
    const int tig  = lane & 3;
    const int wm   = wid & 3;
    const int wn   = wid >> 2;
    const int row0 = blockIdx.x * 128;

    if (tid < 128) { sB1[tid] = b1[tid]; sB2[tid] = b2[tid]; }

    // pre-wait: stage W1 chunk 0 (weights finalized >=1 kernel earlier)
#pragma unroll
    for (int it = 0; it < 2; it++) {
        int i = tid + it * 512;
        int n = i >> 3;
        int q = (i & 7) * 4;
        int gw = n * 64 + q;
        *(uint4*)&sBhi[n * S2 + q] = *(const uint4*)&W1hi[gw];
        *(uint4*)&sBlo[n * S2 + q] = *(const uint4*)&W1lo[gw];
    }

    PDL_WAIT();   // predecessor (h16 producer) now complete

    // stage A full-K [128 rows x 64 words]
#pragma unroll
    for (int it = 0; it < 4; it++) {
        int i = tid + it * 512;
        int r = i >> 4;
        int q = (i & 15) * 4;
        uint4 v = make_uint4(0, 0, 0, 0);
        if (row0 + r < M)
            v = *(const uint4*)&A16[(size_t)(row0 + r) * 64 + q];
        *(uint4*)&sA[r * S2F + q] = v;
    }

    float acc[2][4][4];
#pragma unroll
    for (int i = 0; i < 2; i++)
#pragma unroll
        for (int j = 0; j < 4; j++)
#pragma unroll
            for (int q = 0; q < 4; q++) acc[i][j][q] = 0.f;

    // ================= GEMM 1 =================
    for (int ch = 0; ch < 2; ch++) {
        if (ch) {
            __syncthreads();
            // stage W1 chunk 1
#pragma unroll
            for (int it = 0; it < 2; it++) {
                int i = tid + it * 512;
                int n = i >> 3;
                int q = (i & 7) * 4;
                int gw = n * 64 + 32 + q;
                *(uint4*)&sBhi[n * S2 + q] = *(const uint4*)&W1hi[gw];
                *(uint4*)&sBlo[n * S2 + q] = *(const uint4*)&W1lo[gw];
            }
        }
        __syncthreads();
#pragma unroll
        for (int ks = 0; ks < 4; ks++) {
            const int kb = ks * 8;
            uint32_t aH[2][4];
#pragma unroll
            for (int mt = 0; mt < 2; mt++) {
                int base = (wm * 32 + mt * 16 + grp) * S2F + ch * 32 + kb + tig;
                aH[mt][0] = sA[base];
                aH[mt][1] = sA[base + 8 * S2F];
                aH[mt][2] = sA[base + 4];
                aH[mt][3] = sA[base + 8 * S2F + 4];
            }
#pragma unroll
            for (int nt = 0; nt < 4; nt++) {
                int bb = (wn * 32 + nt * 8 + grp) * S2 + kb + tig;
                uint32_t bh0 = sBhi[bb], bh1 = sBhi[bb + 4];
                uint32_t bl0 = sBlo[bb], bl1 = sBlo[bb + 4];
#pragma unroll
                for (int mt = 0; mt < 2; mt++) {
                    mma_f16(acc[mt][nt], aH[mt], bh0, bh1);
                    mma_f16(acc[mt][nt], aH[mt], bl0, bl1);
                }
            }
        }
    }
    __syncthreads();

    // hidden = relu(acc + b1) -> overwrite sA
#pragma unroll
    for (int mt = 0; mt < 2; mt++) {
        int lr = wm * 32 + mt * 16 + grp;
#pragma unroll
        for (int nt = 0; nt < 4; nt++) {
            int col = wn * 32 + nt * 8 + 2 * tig;
            float b0 = sB1[col], bq = sB1[col + 1];
            float v0 = fmaxf(acc[mt][nt][0] + b0, 0.f);
            float v1 = fmaxf(acc[mt][nt][1] + bq, 0.f);
            float v2 = fmaxf(acc[mt][nt][2] + b0, 0.f);
            float v3 = fmaxf(acc[mt][nt][3] + bq, 0.f);
            sA[lr * S2F + (col >> 1)]       = pack2(__float2half_rn(v0), __float2half_rn(v1));
            sA[(lr + 8) * S2F + (col >> 1)] = pack2(__float2half_rn(v2), __float2half_rn(v3));
            acc[mt][nt][0] = 0.f; acc[mt][nt][1] = 0.f;
            acc[mt][nt][2] = 0.f; acc[mt][nt][3] = 0.f;
        }
    }

    // ================= GEMM 2 =================
    for (int ch = 0; ch < 2; ch++) {
        if (ch) __syncthreads();
#pragma unroll
        for (int it = 0; it < 2; it++) {
            int i = tid + it * 512;
            int n = i >> 3;
            int q = (i & 7) * 4;
            int gw = n * 64 + ch * 32 + q;
            *(uint4*)&sBhi[n * S2 + q] = *(const uint4*)&W2hi[gw];
            *(uint4*)&sBlo[n * S2 + q] = *(const uint4*)&W2lo[gw];
        }
        __syncthreads();
#pragma unroll
        for (int ks = 0; ks < 4; ks++) {
            const int kb = ks * 8;
            uint32_t aH[2][4];
#pragma unroll
            for (int mt = 0; mt < 2; mt++) {
                int base = (wm * 32 + mt * 16 + grp) * S2F + ch * 32 + kb + tig;
                aH[mt][0] = sA[base];
                aH[mt][1] = sA[base + 8 * S2F];
                aH[mt][2] = sA[base + 4];
                aH[mt][3] = sA[base + 8 * S2F + 4];
            }
#pragma unroll
            for (int nt = 0; nt < 4; nt++) {
                int bb = (wn * 32 + nt * 8 + grp) * S2 + kb + tig;
                uint32_t bh0 = sBhi[bb], bh1 = sBhi[bb + 4];
                uint32_t bl0 = sBlo[bb], bl1 = sBlo[bb + 4];
#pragma unroll
                for (int mt = 0; mt < 2; mt++) {
                    mma_f16(acc[mt][nt], aH[mt], bh0, bh1);
                    mma_f16(acc[mt][nt], aH[mt], bl0, bl1);
                }
            }
        }
    }

    // epilogue: relu(acc + b2) * invs -> xs16
#pragma unroll
    for (int mt = 0; mt < 2; mt++) {
        int ra = row0 + wm * 32 + mt * 16 + grp;
        int rb = ra + 8;
        float sa = (ra < M) ? g_invs[ra] : 0.f;
        float sb = (rb < M) ? g_invs[rb] : 0.f;
#pragma unroll
        for (int nt = 0; nt < 4; nt++) {
            int col = wn * 32 + nt * 8 + 2 * tig;
            float b0 = sB2[col], bq = sB2[col + 1];
            float v0 = fmaxf(acc[mt][nt][0] + b0, 0.f) * sa;
            float v1 = fmaxf(acc[mt][nt][1] + bq, 0.f) * sa;
            float v2 = fmaxf(acc[mt][nt][2] + b0, 0.f) * sb;
            float v3 = fmaxf(acc[mt][nt][3] + bq, 0.f) * sb;
            __half2 pa2 = __floats2half2_rn(v0, v1);
            __half2 pb2 = __floats2half2_rn(v2, v3);
            if (ra < M) C16[(size_t)ra * 64 + (col >> 1)] = *(uint32_t*)&pa2;
            if (rb < M) C16[(size_t)rb * 64 + (col >> 1)] = *(uint32_t*)&pb2;
        }
    }
}
#define SM_MLP ((128 * S2F + 2 * TILEW) * 4 + 256 * 4)

// ---------------- fused CSR gather (fp16) + skip + LayerNorm (fp16 h) ----------------
// R10 body; PDL trigger at entry, CSR offsets pre-wait, xs/h reads post-wait.
__global__ __launch_bounds__(256)
void k_gln(const uint32_t* __restrict__ xs16, uint32_t* __restrict__ h16,
           const float* __restrict__ scale, const float* __restrict__ offset) {
    PDL_TRIGGER();
    int node = (blockIdx.x * blockDim.x + threadIdx.x) >> 5;
    int lane = threadIdx.x & 31;
    if (node >= N_NODES) { PDL_WAIT(); return; }
    const int c = lane * 4;
    const int w = lane * 2;

    // pre-wait: CSR topology (guarded by evJoin stream dependency, not by predecessor)
    const int beg = g_start[node];
    const int end = beg + g_cr[node];

    PDL_WAIT();   // xs16 producer complete

    float4 acc;
    {
        uint2 sv = *(const uint2*)&xs16[(size_t)node * 64 + w];
        float2 f0 = __half22float2(*(__half2*)&sv.x);
        float2 f1 = __half22float2(*(__half2*)&sv.y);
        acc = make_float4(f0.x, f0.y, f1.x, f1.y);
    }

    for (int base = beg; base < end; base += 32) {
        int idx = (base + lane < end) ? g_csr[base + lane] : 0;
        int m = min(32, end - base);
        int j = 0;
        for (; j + 4 <= m; j += 4) {
            int s0 = __shfl_sync(0xffffffffu, idx, j);
            int s1 = __shfl_sync(0xffffffffu, idx, j + 1);
            int s2 = __shfl_sync(0xffffffffu, idx, j + 2);
            int s3 = __shfl_sync(0xffffffffu, idx, j + 3);
            uint2 v0 = *(const uint2*)&xs16[(size_t)s0 * 64 + w];
            uint2 v1 = *(const uint2*)&xs16[(size_t)s1 * 64 + w];
            uint2 v2 = *(const uint2*)&xs16[(size_t)s2 * 64 + w];
            uint2 v3 = *(const uint2*)&xs16[(size_t)s3 * 64 + w];
            float2 e;
            e = __half22float2(*(__half2*)&v0.x); acc.x += e.x; acc.y += e.y;
            e = __half22float2(*(__half2*)&v1.x); acc.x += e.x; acc.y += e.y;
            e = __half22float2(*(__half2*)&v2.x); acc.x += e.x; acc.y += e.y;
            e = __half22float2(*(__half2*)&v3.x); acc.x += e.x; acc.y += e.y;
            e = __half22float2(*(__half2*)&v0.y); acc.z += e.x; acc.w += e.y;
            e = __half22float2(*(__half2*)&v1.y); acc.z += e.x; acc.w += e.y;
            e = __half22float2(*(__half2*)&v2.y); acc.z += e.x; acc.w += e.y;
            e = __half22float2(*(__half2*)&v3.y); acc.z += e.x; acc.w += e.y;
        }
        for (; j < m; j++) {
            int s = __shfl_sync(0xffffffffu, idx, j);
            uint2 v = *(const uint2*)&xs16[(size_t)s * 64 + w];
            float2 f0 = __half22float2(*(__half2*)&v.x);
            float2 f1 = __half22float2(*(__half2*)&v.y);
            acc.x += f0.x; acc.y += f0.y; acc.z += f1.x; acc.w += f1.y;
        }
    }

    float ir = g_invr[node];
    float4 vh;
    {
        uint2 hv = *(const uint2*)&h16[(size_t)node * 64 + w];
        float2 f0 = __half22float2(*(__half2*)&hv.x);
        float2 f1 = __half22float2(*(__half2*)&hv.y);
        vh = make_float4(f0.x, f0.y, f1.x, f1.y);
    }
    float4 y;
    y.x = acc.x * ir + vh.x; y.y = acc.y * ir + vh.y;
    y.z = acc.z * ir + vh.z; y.w = acc.w * ir + vh.w;

    float sum = y.x + y.y + y.z + y.w;
    float sq  = y.x * y.x + y.y * y.y + y.z * y.z + y.w * y.w;
#pragma unroll
    for (int o = 16; o; o >>= 1) {
        sum += __shfl_xor_sync(0xffffffffu, sum, o);
        sq  += __shfl_xor_sync(0xffffffffu, sq, o);
    }
    float mean = sum * (1.f / 128.f);
    float var  = sq * (1.f / 128.f) - mean * mean;
    float rs = rsqrtf(var + LN_EPS);
    float4 scv = *(const float4*)&scale[c];
    float4 ofv = *(const float4*)&offset[c];
    y.x = (y.x - mean) * rs * scv.x + ofv.x;
    y.y = (y.y - mean) * rs * scv.y + ofv.y;
    y.z = (y.z - mean) * rs * scv.z + ofv.z;
    y.w = (y.w - mean) * rs * scv.w + ofv.w;
    __half2 p0 = __floats2half2_rn(y.x, y.y);
    __half2 p1 = __floats2half2_rn(y.z, y.w);
    *(uint2*)&h16[(size_t)node * 64 + w] = make_uint2(*(uint32_t*)&p0, *(uint32_t*)&p1);
}

// ---------------- pool (fp16 h) + decode ----------------
__global__ __launch_bounds__(64)
void k_pool(const uint32_t* __restrict__ h16, const float* __restrict__ dec_w,
            const float* __restrict__ dec_b, float* __restrict__ out) {
    PDL_TRIGGER();
    int g = blockIdx.x;
    int w = threadIdx.x;
    const int per = N_NODES / N_GRAPH;
    const uint32_t* base = h16 + (size_t)g * per * 64;
    // pre-wait: decoder weights (inputs, stable)
    float w0 = dec_w[2 * w], w1 = dec_w[2 * w + 1];
    float bb = dec_b[0];
    PDL_WAIT();
    float s0 = 0.f, s1 = 0.f;
#pragma unroll 8
    for (int r = 0; r < per; r++) {
        uint32_t v = base[(size_t)r * 64 + w];
        float2 f = __half22float2(*(__half2*)&v);
        s0 += f.x; s1 += f.y;
    }
    float val = (s0 * w0 + s1 * w1) * (1.f / (float)per);
    __shared__ float red[2];
#pragma unroll
    for (int o = 16; o; o >>= 1) val += __shfl_xor_sync(0xffffffffu, val, o);
    if ((threadIdx.x & 31) == 0) red[threadIdx.x >> 5] = val;
    __syncthreads();
    if (threadIdx.x == 0) out[g] = red[0] + red[1] + bb;
}

// ---------------- launch ----------------
template<typename... Args>
static void launch_pdl(void (*kern)(Args...), dim3 grid, dim3 block, size_t smem,
                       Args... args) {
    cudaLaunchConfig_t cfg = {};
    cfg.gridDim = grid;
    cfg.blockDim = block;
    cfg.dynamicSmemBytes = smem;
    cfg.stream = 0;
    cudaLaunchAttribute at[1];
    at[0].id = cudaLaunchAttributeProgrammaticStreamSerialization;
    at[0].val.programmaticStreamSerializationAllowed = 1;
    cfg.attrs = at;
    cfg.numAttrs = 1;
    cudaLaunchKernelEx(&cfg, kern, args...);
}

extern "C" void kernel_launch(void* const* d_in, const int* in_sizes, int n_in,
                              void* d_out, int out_size) {
    const float* nodes     = (const float*)d_in[0];
    const int*   senders   = (const int*)d_in[1];
    const int*   receivers = (const int*)d_in[2];
    const float* embed_w   = (const float*)d_in[4];
    const float* embed_b   = (const float*)d_in[5];
    const float* mlp_w     = (const float*)d_in[6];
    const float* mlp_b     = (const float*)d_in[7];
    const float* ln_scale  = (const float*)d_in[8];
    const float* ln_offset = (const float*)d_in[9];
    const float* dec_w     = (const float*)d_in[10];
    const float* dec_b     = (const float*)d_in[11];
    float* out = (float*)d_out;

    uint32_t *ph16, *px16, *pwhi, *pwlo;
    cudaGetSymbolAddress((void**)&ph16, g_h16);
    cudaGetSymbolAddress((void**)&px16, g_x16);
    cudaGetSymbolAddress((void**)&pwhi, g_whi);
    cudaGetSymbolAddress((void**)&pwlo, g_wlo);

    cudaFuncSetAttribute(k_embed, cudaFuncAttributeMaxDynamicSharedMemorySize, SM_EMBED);
    cudaFuncSetAttribute(k_mlp,   cudaFuncAttributeMaxDynamicSharedMemorySize, SM_MLP);

    static cudaStream_t s2 = nullptr;
    static cudaEvent_t evFork = nullptr, evInv = nullptr, evJoin = nullptr;
    if (!s2) {
        cudaStreamCreateWithFlags(&s2, cudaStreamNonBlocking);
        cudaEventCreateWithFlags(&evFork, cudaEventDisableTiming);
        cudaEventCreateWithFlags(&evInv, cudaEventDisableTiming);
        cudaEventCreateWithFlags(&evJoin, cudaEventDisableTiming);
    }

    // ---- fork: CSR build on s2 ----
    cudaEventRecord(evFork, 0);
    cudaStreamWaitEvent(s2, evFork, 0);
    k_zero_deg<<<(N_NODES + 255) / 256, 256, 0, s2>>>();
    k_count<<<(N_EDGES + 255) / 256, 256, 0, s2>>>(senders, receivers);
    k_inv<<<(N_NODES + 255) / 256, 256, 0, s2>>>();
    cudaEventRecord(evInv, s2);
    k_fill<<<(N_EDGES + 255) / 256, 256, 0, s2>>>(senders, receivers);
    cudaEventRecord(evJoin, s2);

    const int gemm_grid = (N_NODES + 127) / 128;

    k_wconv<<<(WCONV_WORDS + 255) / 256, 256>>>(embed_w, mlp_w);
    k_embed<<<gemm_grid, 512, SM_EMBED>>>(nodes, pwhi, pwlo, embed_b, ph16, N_NODES);

    const uint32_t* whi_mlp[4];
    const uint32_t* wlo_mlp[4];
    for (int g = 0; g < 4; g++) {
        whi_mlp[g] = pwhi + 4096 + g * 8192;
        wlo_mlp[g] = pwlo + 4096 + g * 8192;
    }

    const int row_grid = (N_NODES * 32 + 255) / 256;

    cudaStreamWaitEvent(0, evInv, 0);

    for (int s = 0; s < 2; s++) {
        const float* b0 = mlp_b + (size_t)(s * 2 + 0) * LATENT;
        const float* b1 = mlp_b + (size_t)(s * 2 + 1) * LATENT;

        launch_pdl(k_mlp, dim3(gemm_grid), dim3(512), (size_t)SM_MLP,
                   (const uint32_t*)ph16,
                   whi_mlp[s * 2], wlo_mlp[s * 2],
                   whi_mlp[s * 2 + 1], wlo_mlp[s * 2 + 1],
                   b0, b1, px16, (int)N_NODES);
        if (s == 0) cudaStreamWaitEvent(0, evJoin, 0);
        launch_pdl(k_gln, dim3(row_grid), dim3(256), (size_t)0,
                   (const uint32_t*)px16, ph16,
                   (const float*)(ln_scale + s * LATENT),
                   (const float*)(ln_offset + s * LATENT));
    }

    launch_pdl(k_pool, dim3(N_GRAPH), dim3(64), (size_t)0,
               (const uint32_t*)ph16, dec_w, dec_b, out);
}